// round 2
// baseline (speedup 1.0000x reference)
#include <cuda_runtime.h>
#include <math.h>

#define B_   2
#define S_   2048
#define E_   4096
#define H_   32
#define HKV_ 8
#define D_   128
#define M_   (B_*S_)   // 4096 tokens

// ---------------- scratch (device globals; no allocation allowed) ----------
__device__ float g_q[M_ * E_];            // [B,S,H,D]  = 16M floats
__device__ float g_k[M_ * HKV_ * D_];     // [B,S,HKV,D] = 4M
__device__ float g_v[M_ * HKV_ * D_];     // 4M
__device__ float g_ctx[M_ * E_];          // [B,S,H,D] = 16M

// ---------------------------------------------------------------------------
// Generic SGEMM + bias: C[M,N] = A[M,K] @ B[K,N] + bias[N]
// 128x128 tile, BK=8, 256 threads, 8x8 register tile per thread.
// All dims here are multiples of the tile sizes (4096 / 1024 / 4096).
// ---------------------------------------------------------------------------
__global__ __launch_bounds__(256) void sgemm_bias_kernel(
    const float* __restrict__ A, const float* __restrict__ Bm,
    const float* __restrict__ bias, float* __restrict__ C,
    int M, int N, int K)
{
    __shared__ float As[8][128];
    __shared__ float Bs[8][128];

    const int tid  = threadIdx.x;
    const int brow = blockIdx.y * 128;
    const int bcol = blockIdx.x * 128;

    const int a_row = tid >> 1;          // 0..127
    const int a_col = (tid & 1) * 4;     // 0 or 4
    const int b_row = tid >> 5;          // 0..7
    const int b_col = (tid & 31) * 4;    // 0..124

    const int ty = tid >> 4;             // 0..15  (8 rows each)
    const int tx = tid & 15;             // 0..15  (8 cols each)

    float acc[8][8];
#pragma unroll
    for (int i = 0; i < 8; i++)
#pragma unroll
        for (int j = 0; j < 8; j++) acc[i][j] = 0.0f;

    for (int k0 = 0; k0 < K; k0 += 8) {
        float4 av = *(const float4*)(A + (size_t)(brow + a_row) * K + k0 + a_col);
        As[a_col + 0][a_row] = av.x;
        As[a_col + 1][a_row] = av.y;
        As[a_col + 2][a_row] = av.z;
        As[a_col + 3][a_row] = av.w;
        *(float4*)(&Bs[b_row][b_col]) =
            *(const float4*)(Bm + (size_t)(k0 + b_row) * N + bcol + b_col);
        __syncthreads();

#pragma unroll
        for (int kk = 0; kk < 8; kk++) {
            float4 a0 = *(float4*)(&As[kk][ty * 8]);
            float4 a1 = *(float4*)(&As[kk][ty * 8 + 4]);
            float4 b0 = *(float4*)(&Bs[kk][tx * 8]);
            float4 b1 = *(float4*)(&Bs[kk][tx * 8 + 4]);
            float ar[8] = {a0.x, a0.y, a0.z, a0.w, a1.x, a1.y, a1.z, a1.w};
            float br[8] = {b0.x, b0.y, b0.z, b0.w, b1.x, b1.y, b1.z, b1.w};
#pragma unroll
            for (int i = 0; i < 8; i++)
#pragma unroll
                for (int j = 0; j < 8; j++)
                    acc[i][j] = fmaf(ar[i], br[j], acc[i][j]);
        }
        __syncthreads();
    }

#pragma unroll
    for (int i = 0; i < 8; i++) {
        const int r = brow + ty * 8 + i;
#pragma unroll
        for (int j = 0; j < 8; j += 4) {
            const int c = bcol + tx * 8 + j;
            float4 o;
            o.x = acc[i][j + 0] + bias[c + 0];
            o.y = acc[i][j + 1] + bias[c + 1];
            o.z = acc[i][j + 2] + bias[c + 2];
            o.w = acc[i][j + 3] + bias[c + 3];
            *(float4*)(C + (size_t)r * N + c) = o;
        }
    }
}

// ---------------------------------------------------------------------------
// Fused interleave-to-half + RoPE, in place. One warp per head (128 elems).
// out[j]    = t[2j]*cos(p*f_j) - t[2j+1]*sin(p*f_j)
// out[j+64] = t[2j]*sin(p*f_j) + t[2j+1]*cos(p*f_j),  f_j = 10000^{-j/64}
// ---------------------------------------------------------------------------
__global__ __launch_bounds__(256) void rope_kernel(float* __restrict__ t,
                                                   int total_heads, int nh)
{
    const int gw = (blockIdx.x * blockDim.x + threadIdx.x) >> 5;
    if (gw >= total_heads) return;
    const int lane = threadIdx.x & 31;
    const int s = (gw / nh) % S_;

    float* base = t + (size_t)gw * 128;
    // j = lane and j = lane+32; read both pairs BEFORE any lane writes
    float e0 = base[2 * lane],      o0 = base[2 * lane + 1];
    float e1 = base[2 * lane + 64], o1 = base[2 * lane + 65];
    __syncwarp();

    const float pos = (float)s;
    const float f0 = powf(10000.0f, -((float)lane) / 64.0f);
    const float f1 = powf(10000.0f, -((float)(lane + 32)) / 64.0f);
    float s0, c0, s1, c1;
    sincosf(pos * f0, &s0, &c0);
    sincosf(pos * f1, &s1, &c1);

    base[lane]      = e0 * c0 - o0 * s0;
    base[lane + 64] = e0 * s0 + o0 * c0;
    base[lane + 32] = e1 * c1 - o1 * s1;
    base[lane + 96] = e1 * s1 + o1 * c1;
}

// ---------------------------------------------------------------------------
// Causal flash attention, fp32, GQA (4 q-heads per kv-head).
// grid = (32 q-tiles, 64 b*h), 256 threads, tiles 64(q) x 64(kv), D=128.
// SMEM: Qs[128][64] (k-major), Ks[128][64] (k-major), Vs[64][128],
//       Ss[64][68], m/l/alpha[64]  -> ~114 KB dynamic.
// Thread grid 16x16: each thread owns 4 q-rows; 4 kv-cols (S phase),
// 8 d-cols (PV phase).
// ---------------------------------------------------------------------------
#define FA_SMEM_FLOATS (128*64 + 128*64 + 64*128 + 64*68 + 3*64)

__global__ __launch_bounds__(256) void flash_kernel(
    const float* __restrict__ q, const float* __restrict__ k,
    const float* __restrict__ v, float* __restrict__ ctx)
{
    extern __shared__ float sm[];
    float* Qs  = sm;                  // [128][64]
    float* Ks  = Qs + 128 * 64;       // [128][64]
    float* Vs  = Ks + 128 * 64;       // [64][128]
    float* Ss  = Vs + 64 * 128;       // [64][68]
    float* mrow = Ss + 64 * 68;       // [64]
    float* lrow = mrow + 64;          // [64]
    float* arow = lrow + 64;          // [64]

    const int tid = threadIdx.x;
    const int qt  = blockIdx.x;       // 0..31
    const int bh  = blockIdx.y;       // 0..63
    const int b   = bh >> 5;          // /H
    const int h   = bh & 31;
    const int hkv = h >> 2;           // H/HKV = 4

    const float* qbase = q + ((size_t)(b * S_ + qt * 64) * H_ + h) * D_;     // row stride 4096
    const float* kbase = k + ((size_t)(b * S_) * HKV_ + hkv) * D_;           // row stride 1024
    const float* vbase = v + ((size_t)(b * S_) * HKV_ + hkv) * D_;

    const int tq = tid >> 4;          // 0..15
    const int tk = tid & 15;          // 0..15

    // Load Q tile transposed into Qs[d][qrow]
    for (int idx = tid; idx < 64 * 32; idx += 256) {
        const int row = idx & 63;
        const int dq  = idx >> 6;     // float4 group
        float4 val = *(const float4*)(qbase + (size_t)row * (H_ * D_) + dq * 4);
        Qs[(dq * 4 + 0) * 64 + row] = val.x;
        Qs[(dq * 4 + 1) * 64 + row] = val.y;
        Qs[(dq * 4 + 2) * 64 + row] = val.z;
        Qs[(dq * 4 + 3) * 64 + row] = val.w;
    }
    if (tid < 64) { mrow[tid] = -INFINITY; lrow[tid] = 0.0f; }

    float o[4][8];
#pragma unroll
    for (int i = 0; i < 4; i++)
#pragma unroll
        for (int j = 0; j < 8; j++) o[i][j] = 0.0f;

    const float scale = 0.08838834764831845f; // 1/sqrt(128)

    for (int jt = 0; jt <= qt; jt++) {
        __syncthreads();  // protect Ks/Vs (prev iter consumers done)

        // Load K tile transposed: Ks[d][kk]
        const float* ktile = kbase + (size_t)(jt * 64) * (HKV_ * D_);
        for (int idx = tid; idx < 64 * 32; idx += 256) {
            const int kk = idx & 63;
            const int dq = idx >> 6;
            float4 val = *(const float4*)(ktile + (size_t)kk * (HKV_ * D_) + dq * 4);
            Ks[(dq * 4 + 0) * 64 + kk] = val.x;
            Ks[(dq * 4 + 1) * 64 + kk] = val.y;
            Ks[(dq * 4 + 2) * 64 + kk] = val.z;
            Ks[(dq * 4 + 3) * 64 + kk] = val.w;
        }
        // Load V tile natural: Vs[kk][d] (coalesced)
        const float* vtile = vbase + (size_t)(jt * 64) * (HKV_ * D_);
        for (int idx = tid; idx < 64 * 32; idx += 256) {
            const int dq = idx & 31;
            const int kk = idx >> 5;
            *(float4*)(&Vs[kk * 128 + dq * 4]) =
                *(const float4*)(vtile + (size_t)kk * (HKV_ * D_) + dq * 4);
        }
        __syncthreads();

        // S = Q @ K^T  (each thread 4x4)
        float accS[4][4];
#pragma unroll
        for (int i = 0; i < 4; i++)
#pragma unroll
            for (int j = 0; j < 4; j++) accS[i][j] = 0.0f;

#pragma unroll 4
        for (int kd = 0; kd < 128; kd++) {
            float4 aq = *(float4*)(&Qs[kd * 64 + tq * 4]);
            float4 bk = *(float4*)(&Ks[kd * 64 + tk * 4]);
            float ar[4] = {aq.x, aq.y, aq.z, aq.w};
            float br[4] = {bk.x, bk.y, bk.z, bk.w};
#pragma unroll
            for (int i = 0; i < 4; i++)
#pragma unroll
                for (int j = 0; j < 4; j++)
                    accS[i][j] = fmaf(ar[i], br[j], accS[i][j]);
        }

        // scale + causal mask (only diagonal tile needs masking) -> Ss
        const int qg0 = qt * 64 + tq * 4;
        const int kg0 = jt * 64 + tk * 4;
#pragma unroll
        for (int i = 0; i < 4; i++) {
#pragma unroll
            for (int j = 0; j < 4; j++) {
                float sv = accS[i][j] * scale;
                if (jt == qt && (kg0 + j) > (qg0 + i)) sv = -1e30f;
                Ss[(tq * 4 + i) * 68 + tk * 4 + j] = sv;
            }
        }
        __syncthreads();

        // Online softmax: one thread per q-row
        if (tid < 64) {
            const int r = tid;
            float mold = mrow[r];
            float mx = mold;
            for (int c = 0; c < 64; c++) mx = fmaxf(mx, Ss[r * 68 + c]);
            float alpha = expf(mold - mx);
            float sum = 0.0f;
            for (int c = 0; c < 64; c++) {
                float p = expf(Ss[r * 68 + c] - mx);
                Ss[r * 68 + c] = p;
                sum += p;
            }
            lrow[r] = lrow[r] * alpha + sum;
            mrow[r] = mx;
            arow[r] = alpha;
        }
        __syncthreads();

        // Rescale O and accumulate P @ V
        float alr[4];
#pragma unroll
        for (int i = 0; i < 4; i++) alr[i] = arow[tq * 4 + i];
#pragma unroll
        for (int i = 0; i < 4; i++)
#pragma unroll
            for (int j = 0; j < 8; j++) o[i][j] *= alr[i];

#pragma unroll 2
        for (int kk = 0; kk < 64; kk++) {
            float4 v0 = *(float4*)(&Vs[kk * 128 + tk * 8]);
            float4 v1 = *(float4*)(&Vs[kk * 128 + tk * 8 + 4]);
#pragma unroll
            for (int i = 0; i < 4; i++) {
                float p = Ss[(tq * 4 + i) * 68 + kk];
                o[i][0] = fmaf(p, v0.x, o[i][0]);
                o[i][1] = fmaf(p, v0.y, o[i][1]);
                o[i][2] = fmaf(p, v0.z, o[i][2]);
                o[i][3] = fmaf(p, v0.w, o[i][3]);
                o[i][4] = fmaf(p, v1.x, o[i][4]);
                o[i][5] = fmaf(p, v1.y, o[i][5]);
                o[i][6] = fmaf(p, v1.z, o[i][6]);
                o[i][7] = fmaf(p, v1.w, o[i][7]);
            }
        }
    }
    __syncthreads();

    // Epilogue: normalize and write ctx[b][s][h][d]
#pragma unroll
    for (int i = 0; i < 4; i++) {
        const float inv = 1.0f / lrow[tq * 4 + i];
        const int qg = qt * 64 + tq * 4 + i;
        float* outp = ctx + ((size_t)(b * S_ + qg) * H_ + h) * D_ + tk * 8;
        float4 w0, w1;
        w0.x = o[i][0] * inv; w0.y = o[i][1] * inv;
        w0.z = o[i][2] * inv; w0.w = o[i][3] * inv;
        w1.x = o[i][4] * inv; w1.y = o[i][5] * inv;
        w1.z = o[i][6] * inv; w1.w = o[i][7] * inv;
        *(float4*)(outp)     = w0;
        *(float4*)(outp + 4) = w1;
    }
}

// ---------------------------------------------------------------------------
extern "C" void kernel_launch(void* const* d_in, const int* in_sizes, int n_in,
                              void* d_out, int out_size)
{
    const float* x    = (const float*)d_in[0];
    const float* wq_w = (const float*)d_in[1];
    const float* wq_b = (const float*)d_in[2];
    const float* wk_w = (const float*)d_in[3];
    const float* wk_b = (const float*)d_in[4];
    const float* wv_w = (const float*)d_in[5];
    const float* wv_b = (const float*)d_in[6];
    const float* wo_w = (const float*)d_in[7];
    const float* wo_b = (const float*)d_in[8];

    float *q, *k, *v, *ctx;
    cudaGetSymbolAddress((void**)&q,   g_q);
    cudaGetSymbolAddress((void**)&k,   g_k);
    cudaGetSymbolAddress((void**)&v,   g_v);
    cudaGetSymbolAddress((void**)&ctx, g_ctx);

    // QKV projections
    sgemm_bias_kernel<<<dim3(32, 32), 256>>>(x, wq_w, wq_b, q,   M_, E_,        E_);
    sgemm_bias_kernel<<<dim3(8,  32), 256>>>(x, wk_w, wk_b, k,   M_, HKV_ * D_, E_);
    sgemm_bias_kernel<<<dim3(8,  32), 256>>>(x, wv_w, wv_b, v,   M_, HKV_ * D_, E_);

    // RoPE on q and k (in place)
    rope_kernel<<<(M_ * H_   * 32) / 256, 256>>>(q, M_ * H_,   H_);
    rope_kernel<<<(M_ * HKV_ * 32) / 256, 256>>>(k, M_ * HKV_, HKV_);

    // Flash attention
    const int fa_smem = FA_SMEM_FLOATS * (int)sizeof(float);
    cudaFuncSetAttribute(flash_kernel, cudaFuncAttributeMaxDynamicSharedMemorySize, fa_smem);
    flash_kernel<<<dim3(32, 64), 256, fa_smem>>>(q, k, v, ctx);

    // Output projection -> d_out
    sgemm_bias_kernel<<<dim3(32, 32), 256>>>(ctx, wo_w, wo_b, (float*)d_out, M_, E_, E_);
}

// round 12
// speedup vs baseline: 1.5088x; 1.5088x over previous
#include <cuda_runtime.h>
#include <cuda_bf16.h>
#include <math.h>
#include <stdint.h>

#define B_   2
#define S_   2048
#define E_   4096
#define H_   32
#define HKV_ 8
#define D_   128
#define M_   (B_*S_)   // 4096 tokens
#define NKV_ (HKV_*D_) // 1024

// ---- arch gate: tcgen05 only exists on the arch-specific ('a') target -----
#ifndef __CUDA_ARCH_HAS_FEATURE__
#define __CUDA_ARCH_HAS_FEATURE__(x) 0
#endif
#if defined(__CUDA_ARCH__)
#  if __CUDA_ARCH_HAS_FEATURE__(SM103_ALL) || __CUDA_ARCH_HAS_FEATURE__(SM100_ALL) || \
      __CUDA_ARCH_HAS_FEATURE__(SM101_ALL) || defined(__CUDA_ARCH_SPECIFIC__)
#    define TC_OK 1
#  else
#    define TC_OK 0
#  endif
#else
#  define TC_OK 0
#endif

// ---------------- scratch (device globals; no allocation allowed) ----------
__device__ float g_q[M_ * E_];
__device__ float g_k[M_ * NKV_];
__device__ float g_v[M_ * NKV_];
__device__ float g_ctx[M_ * E_];
// bf16 hi/lo split scratch
__device__ __nv_bfloat16 g_ahi[M_ * E_];
__device__ __nv_bfloat16 g_alo[M_ * E_];
__device__ __nv_bfloat16 g_wqt_hi[E_ * E_];
__device__ __nv_bfloat16 g_wqt_lo[E_ * E_];
__device__ __nv_bfloat16 g_wkt_hi[NKV_ * E_];
__device__ __nv_bfloat16 g_wkt_lo[NKV_ * E_];
__device__ __nv_bfloat16 g_wvt_hi[NKV_ * E_];
__device__ __nv_bfloat16 g_wvt_lo[NKV_ * E_];
__device__ __nv_bfloat16 g_wot_hi[E_ * E_];
__device__ __nv_bfloat16 g_wot_lo[E_ * E_];

// =================== PTX helpers (guarded, sm_103a only) ====================
#if TC_OK
__device__ __forceinline__ uint32_t smem_u32(const void* p) {
    uint32_t a;
    asm("{ .reg .u64 t; cvta.to.shared.u64 t, %1; cvt.u32.u64 %0, t; }"
        : "=r"(a) : "l"(p));
    return a;
}
__device__ __forceinline__ uint32_t elect_one() {
    uint32_t pred;
    asm volatile(
        "{\n\t.reg .pred p;\n\t"
        "elect.sync _|p, 0xFFFFFFFF;\n\t"
        "selp.b32 %0, 1, 0, p;\n\t}"
        : "=r"(pred));
    return pred;
}
__device__ __forceinline__ uint64_t mk_sw128_desc(uint32_t addr) {
    const uint64_t BASE = (uint64_t(2) << 61)   // SW128
                        | (uint64_t(1) << 46)   // version=1 (Blackwell)
                        | (uint64_t(64) << 32)  // SBO = 64 (1024B per 8-row group)
                        | (uint64_t(1) << 16);  // LBO = 1
    return BASE | ((addr >> 4) & 0x3FFF);
}
// TS-mode f16 MMA: A in TMEM, B in SMEM (validated form: test_mma[_iter].cu)
__device__ __forceinline__ void tc_mma_f16_ts(uint32_t d, uint32_t a_tmem,
                                              uint64_t bd, uint32_t idesc,
                                              uint32_t en) {
    asm volatile(
        "{\n\t.reg .pred p;\n\tsetp.ne.u32 p, %4, 0;\n\t"
        "tcgen05.mma.cta_group::1.kind::f16 [%0], [%1], %2, %3, {%5,%5,%5,%5}, p;\n\t}"
        :: "r"(d), "r"(a_tmem), "l"(bd), "r"(idesc), "r"(en), "r"(0u) : "memory");
}
__device__ __forceinline__ void tc_commit(uint32_t mbar) {
    asm volatile(
        "tcgen05.commit.cta_group::1.mbarrier::arrive::one.shared::cluster.b64 [%0];"
        :: "r"(mbar) : "memory");
}
__device__ __forceinline__ void mbar_init(uint32_t a, uint32_t cnt) {
    asm volatile("mbarrier.init.shared.b64 [%0], %1;" :: "r"(a), "r"(cnt) : "memory");
}
__device__ __forceinline__ void mbar_wait(uint32_t a, uint32_t parity) {
    uint32_t done;
    asm volatile(
        "{\n\t.reg .pred p;\n\t"
        "mbarrier.try_wait.parity.acquire.cta.shared::cta.b64 p, [%1], %2;\n\t"
        "selp.b32 %0, 1, 0, p;\n\t}"
        : "=r"(done) : "r"(a), "r"(parity) : "memory");
    if (!done) {
        asm volatile(
            "{\n\t.reg .pred P1;\n\t"
            "WAIT_LOOP_%=:\n\t"
            "mbarrier.try_wait.parity.acquire.cta.shared::cta.b64 P1, [%0], %1, 0x989680;\n\t"
            "@P1 bra.uni WAIT_DONE_%=;\n\t"
            "bra.uni WAIT_LOOP_%=;\n\t"
            "WAIT_DONE_%=:\n\t}"
            :: "r"(a), "r"(parity) : "memory");
    }
}
#define TC_ALLOC(sm, n)   asm volatile("tcgen05.alloc.cta_group::1.sync.aligned.shared::cta.b32 [%0], %1;" :: "r"(sm), "r"((uint32_t)(n)) : "memory")
#define TC_DEALLOC(t, n)  asm volatile("tcgen05.dealloc.cta_group::1.sync.aligned.b32 %0, %1;" :: "r"(t), "r"((uint32_t)(n)))
#define TC_FENCE_AFTER()  asm volatile("tcgen05.fence::after_thread_sync;" ::: "memory")
#define TC_FENCE_BEFORE() asm volatile("tcgen05.fence::before_thread_sync;" ::: "memory")
#define TC_WAIT_LD()      asm volatile("tcgen05.wait::ld.sync.aligned;" ::: "memory")
#define TC_WAIT_ST()      asm volatile("tcgen05.wait::st.sync.aligned;" ::: "memory")
#define FENCE_PROXY_ASYNC() asm volatile("fence.proxy.async.shared::cta;" ::: "memory")

#define TCLD32(r, ta) \
    asm volatile( \
        "tcgen05.ld.sync.aligned.32x32b.x32.b32 " \
        "{%0, %1, %2, %3, %4, %5, %6, %7, " \
        " %8, %9, %10, %11, %12, %13, %14, %15, " \
        " %16, %17, %18, %19, %20, %21, %22, %23, " \
        " %24, %25, %26, %27, %28, %29, %30, %31}, [%32];" \
        : "=r"((r)[0]),  "=r"((r)[1]),  "=r"((r)[2]),  "=r"((r)[3]), \
          "=r"((r)[4]),  "=r"((r)[5]),  "=r"((r)[6]),  "=r"((r)[7]), \
          "=r"((r)[8]),  "=r"((r)[9]),  "=r"((r)[10]), "=r"((r)[11]), \
          "=r"((r)[12]), "=r"((r)[13]), "=r"((r)[14]), "=r"((r)[15]), \
          "=r"((r)[16]), "=r"((r)[17]), "=r"((r)[18]), "=r"((r)[19]), \
          "=r"((r)[20]), "=r"((r)[21]), "=r"((r)[22]), "=r"((r)[23]), \
          "=r"((r)[24]), "=r"((r)[25]), "=r"((r)[26]), "=r"((r)[27]), \
          "=r"((r)[28]), "=r"((r)[29]), "=r"((r)[30]), "=r"((r)[31]) \
        : "r"(ta))

#define TCST32(ta, r) \
    asm volatile( \
        "tcgen05.st.sync.aligned.32x32b.x32.b32 [%0], " \
        "{%1, %2, %3, %4, %5, %6, %7, %8, " \
        " %9, %10, %11, %12, %13, %14, %15, %16, " \
        " %17, %18, %19, %20, %21, %22, %23, %24, " \
        " %25, %26, %27, %28, %29, %30, %31, %32};" \
        :: "r"(ta), \
           "r"((r)[0]),  "r"((r)[1]),  "r"((r)[2]),  "r"((r)[3]), \
           "r"((r)[4]),  "r"((r)[5]),  "r"((r)[6]),  "r"((r)[7]), \
           "r"((r)[8]),  "r"((r)[9]),  "r"((r)[10]), "r"((r)[11]), \
           "r"((r)[12]), "r"((r)[13]), "r"((r)[14]), "r"((r)[15]), \
           "r"((r)[16]), "r"((r)[17]), "r"((r)[18]), "r"((r)[19]), \
           "r"((r)[20]), "r"((r)[21]), "r"((r)[22]), "r"((r)[23]), \
           "r"((r)[24]), "r"((r)[25]), "r"((r)[26]), "r"((r)[27]), \
           "r"((r)[28]), "r"((r)[29]), "r"((r)[30]), "r"((r)[31]) \
        : "memory")
#endif  // TC_OK

// ===========================================================================
// Precision-split conversion:  x = hi(bf16) + lo(bf16), lo exact residual.
// ===========================================================================
__global__ __launch_bounds__(256) void convert_hilo(
    const float* __restrict__ in, __nv_bfloat16* __restrict__ hi,
    __nv_bfloat16* __restrict__ lo, int n4)
{
    int i = blockIdx.x * blockDim.x + threadIdx.x;
    if (i >= n4) return;
    float4 v = ((const float4*)in)[i];
    float vv[4] = {v.x, v.y, v.z, v.w};
    union { __nv_bfloat162 b2[2]; uint2 u; } uh, ul;
#pragma unroll
    for (int e = 0; e < 4; e += 2) {
        __nv_bfloat16 h0 = __float2bfloat16(vv[e]);
        __nv_bfloat16 h1 = __float2bfloat16(vv[e + 1]);
        __nv_bfloat16 l0 = __float2bfloat16(vv[e]     - __bfloat162float(h0));
        __nv_bfloat16 l1 = __float2bfloat16(vv[e + 1] - __bfloat162float(h1));
        uh.b2[e >> 1] = __nv_bfloat162(h0, h1);
        ul.b2[e >> 1] = __nv_bfloat162(l0, l1);
    }
    ((uint2*)hi)[i] = uh.u;
    ((uint2*)lo)[i] = ul.u;
}

// W [K,N] fp32  ->  Wt_hi/lo [N,K] bf16  (transpose + split)
__global__ __launch_bounds__(256) void transpose_convert(
    const float* __restrict__ w, __nv_bfloat16* __restrict__ thi,
    __nv_bfloat16* __restrict__ tlo, int Kdim, int Ndim)
{
    __shared__ float tile[32][33];
    const int nb = blockIdx.x * 32, kb = blockIdx.y * 32;
    const int tx = threadIdx.x, ty = threadIdx.y;   // 32 x 8
#pragma unroll
    for (int i = 0; i < 32; i += 8)
        tile[ty + i][tx] = w[(size_t)(kb + ty + i) * Ndim + nb + tx];
    __syncthreads();
#pragma unroll
    for (int i = 0; i < 32; i += 8) {
        float x = tile[tx][ty + i];
        __nv_bfloat16 h = __float2bfloat16(x);
        __nv_bfloat16 l = __float2bfloat16(x - __bfloat162float(h));
        size_t o = (size_t)(nb + ty + i) * Kdim + kb + tx;
        thi[o] = h;  tlo[o] = l;
    }
}

// ===========================================================================
// tcgen05 GEMM — TS mode (A in TMEM, B in SMEM), the VALIDATED cg1 f16 config
// (test_mma.cu / test_mma_iter.cu skeleton).
// C[M,N] = A[M,K] @ B^T (+bias); A row-major bf16 [M,K], B row-major bf16 [N,K].
// CTA tile 128x128, K-chunk 64, 128 threads. Per chunk:
//   B hi/lo -> SMEM (SW128); A hi/lo row -> regs -> tcgen05.st to TMEM;
//   WAIT_ST + FENCE_BEFORE + syncthreads; warp0 FENCE_AFTER + elected MMAs
//   (a_tmem + ksub*8, b_desc + ksub*2 -- validated offsets) + commit;
//   all threads parity-wait.
// TMEM: 256 cols (D=0..127, Ahi=128..159, Alo=160..191); 2 CTAs/SM (=512).
// SMEM request padded to 98KB to cap occupancy at 2 CTAs/SM.
// ===========================================================================
#define GT_KC     64
#define GT_TILEB  (128 * 128)            // 16 KB per B tile (128 rows x 64 bf16)
#define GT_SMEM_USED (1024 + 2 * GT_TILEB)
#define GT_SMEM   (98 * 1024)            // padded: occupancy cap 2 CTAs/SM
// idesc kind::f16: dtype=F32, a/b=BF16, N=128, M=128 (test_mma field layout)
#define GT_IDESC  ((1u<<4) | (1u<<7) | (1u<<10) | ((128u/8u)<<17) | ((128u/16u)<<24))

__global__ __launch_bounds__(128, 1)
void gemm_tc(const __nv_bfloat16* __restrict__ Ahi,
             const __nv_bfloat16* __restrict__ Alo,
             const __nv_bfloat16* __restrict__ Bhi,
             const __nv_bfloat16* __restrict__ Blo,
             const float* __restrict__ bias, float* __restrict__ C,
             int Mdim, int Ndim, int Kdim)
{
#if TC_OK
    extern __shared__ unsigned char smem[];
    const uint32_t smem_base = smem_u32(smem);
    const int tid  = threadIdx.x;       // 0..127 (one warpgroup)
    const int wid  = tid >> 5;
    const int lane = tid & 31;
    const int brow = blockIdx.y * 128;
    const int bcol = blockIdx.x * 128;
    const int NC   = Kdim / GT_KC;

    // TMEM alloc (warp 0, like test_mma_iter) + mbarrier init
    if (wid == 0) TC_ALLOC(smem_base, 256);
    if (tid == 0) mbar_init(smem_base + 8, 1);
    __syncthreads();
    uint32_t tmem_base;
    asm volatile("ld.shared.b32 %0, [%1];" : "=r"(tmem_base) : "r"(smem_base));

    const uint32_t TD  = tmem_base;         // D: 128 cols
    const uint32_t TAH = tmem_base + 128;   // A hi: 32 cols
    const uint32_t TAL = tmem_base + 160;   // A lo: 32 cols

    const uint64_t dBH = mk_sw128_desc(smem_base + 1024);
    const uint64_t dBL = mk_sw128_desc(smem_base + 1024 + GT_TILEB);

    const uint32_t woff = ((uint32_t)tid >> 5) << 21;  // TMEM subpartition

    for (int c = 0; c < NC; c++) {
        const int k0 = c * GT_KC;

        // ---- B hi/lo tiles -> SMEM with SW128 swizzle (128 threads) --------
#pragma unroll
        for (int t = 0; t < 2; t++) {
            const __nv_bfloat16* s = t ? Blo : Bhi;
            unsigned char* dst = smem + 1024 + t * GT_TILEB;
            for (int i = tid; i < 1024; i += 128) {
                const int r  = i >> 3;
                const int kq = i & 7;
                uint4 val = *(const uint4*)(s + (size_t)(bcol + r) * Kdim + k0 + kq * 8);
                uint32_t off = r * 128 + kq * 16;
                off ^= (off >> 3) & 0x70;
                *(uint4*)(dst + off) = val;
            }
        }

        // ---- A hi/lo row (row = tid) : global -> regs -> TMEM --------------
        {
            uint32_t a_hi[32], a_lo[32];
            const uint4* ph = (const uint4*)(Ahi + (size_t)(brow + tid) * Kdim + k0);
            const uint4* pl = (const uint4*)(Alo + (size_t)(brow + tid) * Kdim + k0);
#pragma unroll
            for (int e = 0; e < 8; e++) {
                uint4 vh = ph[e];
                a_hi[e * 4 + 0] = vh.x; a_hi[e * 4 + 1] = vh.y;
                a_hi[e * 4 + 2] = vh.z; a_hi[e * 4 + 3] = vh.w;
                uint4 vl = pl[e];
                a_lo[e * 4 + 0] = vl.x; a_lo[e * 4 + 1] = vl.y;
                a_lo[e * 4 + 2] = vl.z; a_lo[e * 4 + 3] = vl.w;
            }
            TCST32(TAH + woff, a_hi);
            TCST32(TAL + woff, a_lo);
            TC_WAIT_ST();
        }

        TC_FENCE_BEFORE();
        FENCE_PROXY_ASYNC();
        __syncthreads();

        // ---- MMA issue: warp 0, elected thread (mxf8_ss-identical envelope)
        if (wid == 0) {
            TC_FENCE_AFTER();
            if (elect_one()) {
#pragma unroll
                for (int ksub = 0; ksub < 4; ksub++) {
                    const uint64_t o  = ksub * 2;   // B: 16 bf16 = 32B = 2 units
                    const uint32_t ac = ksub * 8;   // A: 16 bf16 = 8 TMEM cols
                    uint32_t en0 = (c == 0 && ksub == 0) ? 0u : 1u;
                    tc_mma_f16_ts(TD, TAH + ac, dBH + o, GT_IDESC, en0);
                    tc_mma_f16_ts(TD, TAH + ac, dBL + o, GT_IDESC, 1u);
                    tc_mma_f16_ts(TD, TAL + ac, dBH + o, GT_IDESC, 1u);
                }
                tc_commit(smem_base + 8);
            }
        }
        // ---- all threads wait for this chunk's MMA completion --------------
        mbar_wait(smem_base + 8, (uint32_t)(c & 1));
        __syncthreads();
    }

    TC_FENCE_AFTER();

    // epilogue: 4 warps read D (128x128 f32) from TMEM, add bias, store
    {
        const int r = wid * 32 + lane;
        float* crow = C + (size_t)(brow + r) * Ndim + bcol;
#pragma unroll
        for (int cb = 0; cb < 4; cb++) {
            uint32_t dreg[32];
            TCLD32(dreg, TD + cb * 32);
            TC_WAIT_LD();
#pragma unroll
            for (int j = 0; j < 32; j += 4) {
                const int col = cb * 32 + j;
                float4 o;
                o.x = __uint_as_float(dreg[j + 0]) + bias[bcol + col + 0];
                o.y = __uint_as_float(dreg[j + 1]) + bias[bcol + col + 1];
                o.z = __uint_as_float(dreg[j + 2]) + bias[bcol + col + 2];
                o.w = __uint_as_float(dreg[j + 3]) + bias[bcol + col + 3];
                *(float4*)(crow + col) = o;
            }
        }
        TC_FENCE_BEFORE();
    }
    __syncthreads();
    if (wid == 0) TC_DEALLOC(tmem_base, 256);

#else  // -------- portable fallback (non-'a' PTX pass only; never runs) -----
    const int tid  = threadIdx.x;
    const int brow = blockIdx.y * 128;
    const int bcol = blockIdx.x * 128;
    // 128 threads; each handles one output row, 8 cols at a time.
    const int r = brow + tid;
    for (int c0 = 0; c0 < 128; c0 += 8) {
        float acc[8];
#pragma unroll
        for (int j = 0; j < 8; j++) acc[j] = 0.0f;
        for (int kk = 0; kk < Kdim; kk++) {
            float a = __bfloat162float(Ahi[(size_t)r * Kdim + kk])
                    + __bfloat162float(Alo[(size_t)r * Kdim + kk]);
#pragma unroll
            for (int j = 0; j < 8; j++) {
                const int cc = bcol + c0 + j;
                float b = __bfloat162float(Bhi[(size_t)cc * Kdim + kk])
                        + __bfloat162float(Blo[(size_t)cc * Kdim + kk]);
                acc[j] = fmaf(a, b, acc[j]);
            }
        }
#pragma unroll
        for (int j = 0; j < 8; j++)
            C[(size_t)r * Ndim + bcol + c0 + j] = acc[j] + bias[bcol + c0 + j];
    }
#endif
}

// ---------------------------------------------------------------------------
// Fused interleave-to-half + RoPE
// ---------------------------------------------------------------------------
__global__ __launch_bounds__(256) void rope_kernel(float* __restrict__ t,
                                                   int total_heads, int nh)
{
    const int gw = (blockIdx.x * blockDim.x + threadIdx.x) >> 5;
    if (gw >= total_heads) return;
    const int lane = threadIdx.x & 31;
    const int s = (gw / nh) % S_;

    float* base = t + (size_t)gw * 128;
    float e0 = base[2 * lane],      o0 = base[2 * lane + 1];
    float e1 = base[2 * lane + 64], o1 = base[2 * lane + 65];
    __syncwarp();

    const float pos = (float)s;
    const float f0 = powf(10000.0f, -((float)lane) / 64.0f);
    const float f1 = powf(10000.0f, -((float)(lane + 32)) / 64.0f);
    float s0, c0, s1, c1;
    sincosf(pos * f0, &s0, &c0);
    sincosf(pos * f1, &s1, &c1);

    base[lane]      = e0 * c0 - o0 * s0;
    base[lane + 64] = e0 * s0 + o0 * c0;
    base[lane + 32] = e1 * c1 - o1 * s1;
    base[lane + 96] = e1 * s1 + o1 * c1;
}

// ---------------------------------------------------------------------------
// Causal flash attention, fp32 (unchanged; known-good)
// ---------------------------------------------------------------------------
#define FA_SMEM_FLOATS (128*64 + 128*64 + 64*128 + 64*68 + 3*64)

__global__ __launch_bounds__(256) void flash_kernel(
    const float* __restrict__ q, const float* __restrict__ k,
    const float* __restrict__ v, float* __restrict__ ctx)
{
    extern __shared__ float sm[];
    float* Qs  = sm;
    float* Ks  = Qs + 128 * 64;
    float* Vs  = Ks + 128 * 64;
    float* Ss  = Vs + 64 * 128;
    float* mrow = Ss + 64 * 68;
    float* lrow = mrow + 64;
    float* arow = lrow + 64;

    const int tid = threadIdx.x;
    const int qt  = blockIdx.x;
    const int bh  = blockIdx.y;
    const int b   = bh >> 5;
    const int h   = bh & 31;
    const int hkv = h >> 2;

    const float* qbase = q + ((size_t)(b * S_ + qt * 64) * H_ + h) * D_;
    const float* kbase = k + ((size_t)(b * S_) * HKV_ + hkv) * D_;
    const float* vbase = v + ((size_t)(b * S_) * HKV_ + hkv) * D_;

    const int tq = tid >> 4;
    const int tk = tid & 15;

    for (int idx = tid; idx < 64 * 32; idx += 256) {
        const int row = idx & 63;
        const int dq  = idx >> 6;
        float4 val = *(const float4*)(qbase + (size_t)row * (H_ * D_) + dq * 4);
        Qs[(dq * 4 + 0) * 64 + row] = val.x;
        Qs[(dq * 4 + 1) * 64 + row] = val.y;
        Qs[(dq * 4 + 2) * 64 + row] = val.z;
        Qs[(dq * 4 + 3) * 64 + row] = val.w;
    }
    if (tid < 64) { mrow[tid] = -INFINITY; lrow[tid] = 0.0f; }

    float o[4][8];
#pragma unroll
    for (int i = 0; i < 4; i++)
#pragma unroll
        for (int j = 0; j < 8; j++) o[i][j] = 0.0f;

    const float scale = 0.08838834764831845f;

    for (int jt = 0; jt <= qt; jt++) {
        __syncthreads();

        const float* ktile = kbase + (size_t)(jt * 64) * (HKV_ * D_);
        for (int idx = tid; idx < 64 * 32; idx += 256) {
            const int kk = idx & 63;
            const int dq = idx >> 6;
            float4 val = *(const float4*)(ktile + (size_t)kk * (HKV_ * D_) + dq * 4);
            Ks[(dq * 4 + 0) * 64 + kk] = val.x;
            Ks[(dq * 4 + 1) * 64 + kk] = val.y;
            Ks[(dq * 4 + 2) * 64 + kk] = val.z;
            Ks[(dq * 4 + 3) * 64 + kk] = val.w;
        }
        const float* vtile = vbase + (size_t)(jt * 64) * (HKV_ * D_);
        for (int idx = tid; idx < 64 * 32; idx += 256) {
            const int dq = idx & 31;
            const int kk = idx >> 5;
            *(float4*)(&Vs[kk * 128 + dq * 4]) =
                *(const float4*)(vtile + (size_t)kk * (HKV_ * D_) + dq * 4);
        }
        __syncthreads();

        float accS[4][4];
#pragma unroll
        for (int i = 0; i < 4; i++)
#pragma unroll
            for (int j = 0; j < 4; j++) accS[i][j] = 0.0f;

#pragma unroll 4
        for (int kd = 0; kd < 128; kd++) {
            float4 aq = *(float4*)(&Qs[kd * 64 + tq * 4]);
            float4 bk = *(float4*)(&Ks[kd * 64 + tk * 4]);
            float ar[4] = {aq.x, aq.y, aq.z, aq.w};
            float br[4] = {bk.x, bk.y, bk.z, bk.w};
#pragma unroll
            for (int i = 0; i < 4; i++)
#pragma unroll
                for (int j = 0; j < 4; j++)
                    accS[i][j] = fmaf(ar[i], br[j], accS[i][j]);
        }

        const int qg0 = qt * 64 + tq * 4;
        const int kg0 = jt * 64 + tk * 4;
#pragma unroll
        for (int i = 0; i < 4; i++) {
#pragma unroll
            for (int j = 0; j < 4; j++) {
                float sv = accS[i][j] * scale;
                if (jt == qt && (kg0 + j) > (qg0 + i)) sv = -1e30f;
                Ss[(tq * 4 + i) * 68 + tk * 4 + j] = sv;
            }
        }
        __syncthreads();

        if (tid < 64) {
            const int r = tid;
            float mold = mrow[r];
            float mx = mold;
            for (int c = 0; c < 64; c++) mx = fmaxf(mx, Ss[r * 68 + c]);
            float alpha = expf(mold - mx);
            float sum = 0.0f;
            for (int c = 0; c < 64; c++) {
                float p = expf(Ss[r * 68 + c] - mx);
                Ss[r * 68 + c] = p;
                sum += p;
            }
            lrow[r] = lrow[r] * alpha + sum;
            mrow[r] = mx;
            arow[r] = alpha;
        }
        __syncthreads();

        float alr[4];
#pragma unroll
        for (int i = 0; i < 4; i++) alr[i] = arow[tq * 4 + i];
#pragma unroll
        for (int i = 0; i < 4; i++)
#pragma unroll
            for (int j = 0; j < 8; j++) o[i][j] *= alr[i];

#pragma unroll 2
        for (int kk = 0; kk < 64; kk++) {
            float4 v0 = *(float4*)(&Vs[kk * 128 + tk * 8]);
            float4 v1 = *(float4*)(&Vs[kk * 128 + tk * 8 + 4]);
#pragma unroll
            for (int i = 0; i < 4; i++) {
                float p = Ss[(tq * 4 + i) * 68 + kk];
                o[i][0] = fmaf(p, v0.x, o[i][0]);
                o[i][1] = fmaf(p, v0.y, o[i][1]);
                o[i][2] = fmaf(p, v0.z, o[i][2]);
                o[i][3] = fmaf(p, v0.w, o[i][3]);
                o[i][4] = fmaf(p, v1.x, o[i][4]);
                o[i][5] = fmaf(p, v1.y, o[i][5]);
                o[i][6] = fmaf(p, v1.z, o[i][6]);
                o[i][7] = fmaf(p, v1.w, o[i][7]);
            }
        }
    }
    __syncthreads();

#pragma unroll
    for (int i = 0; i < 4; i++) {
        const float inv = 1.0f / lrow[tq * 4 + i];
        const int qg = qt * 64 + tq * 4 + i;
        float* outp = ctx + ((size_t)(b * S_ + qg) * H_ + h) * D_ + tk * 8;
        float4 w0, w1;
        w0.x = o[i][0] * inv; w0.y = o[i][1] * inv;
        w0.z = o[i][2] * inv; w0.w = o[i][3] * inv;
        w1.x = o[i][4] * inv; w1.y = o[i][5] * inv;
        w1.z = o[i][6] * inv; w1.w = o[i][7] * inv;
        *(float4*)(outp)     = w0;
        *(float4*)(outp + 4) = w1;
    }
}

// ---------------------------------------------------------------------------
extern "C" void kernel_launch(void* const* d_in, const int* in_sizes, int n_in,
                              void* d_out, int out_size)
{
    const float* x    = (const float*)d_in[0];
    const float* wq_w = (const float*)d_in[1];
    const float* wq_b = (const float*)d_in[2];
    const float* wk_w = (const float*)d_in[3];
    const float* wk_b = (const float*)d_in[4];
    const float* wv_w = (const float*)d_in[5];
    const float* wv_b = (const float*)d_in[6];
    const float* wo_w = (const float*)d_in[7];
    const float* wo_b = (const float*)d_in[8];

    float *q, *k, *v, *ctx;
    __nv_bfloat16 *ahi, *alo, *wqh, *wql, *wkh, *wkl, *wvh, *wvl, *woh, *wol;
    cudaGetSymbolAddress((void**)&q,   g_q);
    cudaGetSymbolAddress((void**)&k,   g_k);
    cudaGetSymbolAddress((void**)&v,   g_v);
    cudaGetSymbolAddress((void**)&ctx, g_ctx);
    cudaGetSymbolAddress((void**)&ahi, g_ahi);
    cudaGetSymbolAddress((void**)&alo, g_alo);
    cudaGetSymbolAddress((void**)&wqh, g_wqt_hi);
    cudaGetSymbolAddress((void**)&wql, g_wqt_lo);
    cudaGetSymbolAddress((void**)&wkh, g_wkt_hi);
    cudaGetSymbolAddress((void**)&wkl, g_wkt_lo);
    cudaGetSymbolAddress((void**)&wvh, g_wvt_hi);
    cudaGetSymbolAddress((void**)&wvl, g_wvt_lo);
    cudaGetSymbolAddress((void**)&woh, g_wot_hi);
    cudaGetSymbolAddress((void**)&wol, g_wot_lo);

    cudaFuncSetAttribute(gemm_tc, cudaFuncAttributeMaxDynamicSharedMemorySize, GT_SMEM);
    cudaFuncSetAttribute(flash_kernel, cudaFuncAttributeMaxDynamicSharedMemorySize,
                         FA_SMEM_FLOATS * (int)sizeof(float));

    const dim3 tb(32, 8);
    // weight transpose + bf16 split (one pass over the weights)
    transpose_convert<<<dim3(E_ / 32,   E_ / 32), tb>>>(wq_w, wqh, wql, E_, E_);
    transpose_convert<<<dim3(NKV_ / 32, E_ / 32), tb>>>(wk_w, wkh, wkl, E_, NKV_);
    transpose_convert<<<dim3(NKV_ / 32, E_ / 32), tb>>>(wv_w, wvh, wvl, E_, NKV_);
    transpose_convert<<<dim3(E_ / 32,   E_ / 32), tb>>>(wo_w, woh, wol, E_, E_);
    // activation split
    convert_hilo<<<(M_ * E_ / 4) / 256, 256>>>(x, ahi, alo, M_ * E_ / 4);

    // QKV projections on tcgen05 (TS mode)
    gemm_tc<<<dim3(E_ / 128,   M_ / 128), 128, GT_SMEM>>>(ahi, alo, wqh, wql, wq_b, q, M_, E_,   E_);
    gemm_tc<<<dim3(NKV_ / 128, M_ / 128), 128, GT_SMEM>>>(ahi, alo, wkh, wkl, wk_b, k, M_, NKV_, E_);
    gemm_tc<<<dim3(NKV_ / 128, M_ / 128), 128, GT_SMEM>>>(ahi, alo, wvh, wvl, wv_b, v, M_, NKV_, E_);

    // RoPE on q and k (in place)
    rope_kernel<<<(M_ * H_   * 32) / 256, 256>>>(q, M_ * H_,   H_);
    rope_kernel<<<(M_ * HKV_ * 32) / 256, 256>>>(k, M_ * HKV_, HKV_);

    // Flash attention (fp32)
    const int fa_smem = FA_SMEM_FLOATS * (int)sizeof(float);
    flash_kernel<<<dim3(32, 64), 256, fa_smem>>>(q, k, v, ctx);

    // Output projection on tcgen05
    convert_hilo<<<(M_ * E_ / 4) / 256, 256>>>(ctx, ahi, alo, M_ * E_ / 4);
    gemm_tc<<<dim3(E_ / 128, M_ / 128), 128, GT_SMEM>>>(ahi, alo, woh, wol, wo_b,
                                                        (float*)d_out, M_, E_, E_);
}

// round 14
// speedup vs baseline: 2.4588x; 1.6296x over previous
#include <cuda_runtime.h>
#include <cuda_bf16.h>
#include <math.h>
#include <stdint.h>

#define B_   2
#define S_   2048
#define E_   4096
#define H_   32
#define HKV_ 8
#define D_   128
#define M_   (B_*S_)   // 4096 tokens
#define NKV_ (HKV_*D_) // 1024

// ---- arch gate: tcgen05 only exists on the arch-specific ('a') target -----
#ifndef __CUDA_ARCH_HAS_FEATURE__
#define __CUDA_ARCH_HAS_FEATURE__(x) 0
#endif
#if defined(__CUDA_ARCH__)
#  if __CUDA_ARCH_HAS_FEATURE__(SM103_ALL) || __CUDA_ARCH_HAS_FEATURE__(SM100_ALL) || \
      __CUDA_ARCH_HAS_FEATURE__(SM101_ALL) || defined(__CUDA_ARCH_SPECIFIC__)
#    define TC_OK 1
#  else
#    define TC_OK 0
#  endif
#else
#  define TC_OK 0
#endif

// ---------------- scratch (device globals; no allocation allowed) ----------
__device__ float g_q[M_ * E_];
__device__ float g_k[M_ * NKV_];
__device__ float g_v[M_ * NKV_];
__device__ float g_ctx[M_ * E_];
// bf16 hi/lo split scratch
__device__ __nv_bfloat16 g_ahi[M_ * E_];
__device__ __nv_bfloat16 g_alo[M_ * E_];
__device__ __nv_bfloat16 g_wqt_hi[E_ * E_];
__device__ __nv_bfloat16 g_wqt_lo[E_ * E_];
__device__ __nv_bfloat16 g_wkt_hi[NKV_ * E_];
__device__ __nv_bfloat16 g_wkt_lo[NKV_ * E_];
__device__ __nv_bfloat16 g_wvt_hi[NKV_ * E_];
__device__ __nv_bfloat16 g_wvt_lo[NKV_ * E_];
__device__ __nv_bfloat16 g_wot_hi[E_ * E_];
__device__ __nv_bfloat16 g_wot_lo[E_ * E_];

// =================== PTX helpers (guarded, sm_103a only) ====================
#if TC_OK
__device__ __forceinline__ uint32_t smem_u32(const void* p) {
    uint32_t a;
    asm("{ .reg .u64 t; cvta.to.shared.u64 t, %1; cvt.u32.u64 %0, t; }"
        : "=r"(a) : "l"(p));
    return a;
}
__device__ __forceinline__ uint32_t elect_one() {
    uint32_t pred;
    asm volatile(
        "{\n\t.reg .pred p;\n\t"
        "elect.sync _|p, 0xFFFFFFFF;\n\t"
        "selp.b32 %0, 1, 0, p;\n\t}"
        : "=r"(pred));
    return pred;
}
__device__ __forceinline__ uint64_t mk_sw128_desc(uint32_t addr) {
    const uint64_t BASE = (uint64_t(2) << 61)   // SW128
                        | (uint64_t(1) << 46)   // version=1 (Blackwell)
                        | (uint64_t(64) << 32)  // SBO = 64
                        | (uint64_t(1) << 16);  // LBO = 1
    return BASE | ((addr >> 4) & 0x3FFF);
}
// TS-mode f16 MMA: A in TMEM, B in SMEM (validated: test_mma[_iter].cu)
__device__ __forceinline__ void tc_mma_f16_ts(uint32_t d, uint32_t a_tmem,
                                              uint64_t bd, uint32_t idesc,
                                              uint32_t en) {
    asm volatile(
        "{\n\t.reg .pred p;\n\tsetp.ne.u32 p, %4, 0;\n\t"
        "tcgen05.mma.cta_group::1.kind::f16 [%0], [%1], %2, %3, {%5,%5,%5,%5}, p;\n\t}"
        :: "r"(d), "r"(a_tmem), "l"(bd), "r"(idesc), "r"(en), "r"(0u) : "memory");
}
__device__ __forceinline__ void tc_commit(uint32_t mbar) {
    asm volatile(
        "tcgen05.commit.cta_group::1.mbarrier::arrive::one.shared::cluster.b64 [%0];"
        :: "r"(mbar) : "memory");
}
__device__ __forceinline__ void mbar_init(uint32_t a, uint32_t cnt) {
    asm volatile("mbarrier.init.shared.b64 [%0], %1;" :: "r"(a), "r"(cnt) : "memory");
}
__device__ __forceinline__ void mbar_wait(uint32_t a, uint32_t parity) {
    uint32_t done;
    asm volatile(
        "{\n\t.reg .pred p;\n\t"
        "mbarrier.try_wait.parity.acquire.cta.shared::cta.b64 p, [%1], %2;\n\t"
        "selp.b32 %0, 1, 0, p;\n\t}"
        : "=r"(done) : "r"(a), "r"(parity) : "memory");
    if (!done) {
        asm volatile(
            "{\n\t.reg .pred P1;\n\t"
            "WAIT_LOOP_%=:\n\t"
            "mbarrier.try_wait.parity.acquire.cta.shared::cta.b64 P1, [%0], %1, 0x989680;\n\t"
            "@P1 bra.uni WAIT_DONE_%=;\n\t"
            "bra.uni WAIT_LOOP_%=;\n\t"
            "WAIT_DONE_%=:\n\t}"
            :: "r"(a), "r"(parity) : "memory");
    }
}
#define TC_ALLOC(sm, n)   asm volatile("tcgen05.alloc.cta_group::1.sync.aligned.shared::cta.b32 [%0], %1;" :: "r"(sm), "r"((uint32_t)(n)) : "memory")
#define TC_DEALLOC(t, n)  asm volatile("tcgen05.dealloc.cta_group::1.sync.aligned.b32 %0, %1;" :: "r"(t), "r"((uint32_t)(n)))
#define TC_FENCE_AFTER()  asm volatile("tcgen05.fence::after_thread_sync;" ::: "memory")
#define TC_FENCE_BEFORE() asm volatile("tcgen05.fence::before_thread_sync;" ::: "memory")
#define TC_WAIT_LD()      asm volatile("tcgen05.wait::ld.sync.aligned;" ::: "memory")
#define TC_WAIT_ST()      asm volatile("tcgen05.wait::st.sync.aligned;" ::: "memory")
#define FENCE_PROXY_ASYNC() asm volatile("fence.proxy.async.shared::cta;" ::: "memory")

#define TCLD32(r, ta) \
    asm volatile( \
        "tcgen05.ld.sync.aligned.32x32b.x32.b32 " \
        "{%0, %1, %2, %3, %4, %5, %6, %7, " \
        " %8, %9, %10, %11, %12, %13, %14, %15, " \
        " %16, %17, %18, %19, %20, %21, %22, %23, " \
        " %24, %25, %26, %27, %28, %29, %30, %31}, [%32];" \
        : "=r"((r)[0]),  "=r"((r)[1]),  "=r"((r)[2]),  "=r"((r)[3]), \
          "=r"((r)[4]),  "=r"((r)[5]),  "=r"((r)[6]),  "=r"((r)[7]), \
          "=r"((r)[8]),  "=r"((r)[9]),  "=r"((r)[10]), "=r"((r)[11]), \
          "=r"((r)[12]), "=r"((r)[13]), "=r"((r)[14]), "=r"((r)[15]), \
          "=r"((r)[16]), "=r"((r)[17]), "=r"((r)[18]), "=r"((r)[19]), \
          "=r"((r)[20]), "=r"((r)[21]), "=r"((r)[22]), "=r"((r)[23]), \
          "=r"((r)[24]), "=r"((r)[25]), "=r"((r)[26]), "=r"((r)[27]), \
          "=r"((r)[28]), "=r"((r)[29]), "=r"((r)[30]), "=r"((r)[31]) \
        : "r"(ta))

#define TCST32(ta, r) \
    asm volatile( \
        "tcgen05.st.sync.aligned.32x32b.x32.b32 [%0], " \
        "{%1, %2, %3, %4, %5, %6, %7, %8, " \
        " %9, %10, %11, %12, %13, %14, %15, %16, " \
        " %17, %18, %19, %20, %21, %22, %23, %24, " \
        " %25, %26, %27, %28, %29, %30, %31, %32};" \
        :: "r"(ta), \
           "r"((r)[0]),  "r"((r)[1]),  "r"((r)[2]),  "r"((r)[3]), \
           "r"((r)[4]),  "r"((r)[5]),  "r"((r)[6]),  "r"((r)[7]), \
           "r"((r)[8]),  "r"((r)[9]),  "r"((r)[10]), "r"((r)[11]), \
           "r"((r)[12]), "r"((r)[13]), "r"((r)[14]), "r"((r)[15]), \
           "r"((r)[16]), "r"((r)[17]), "r"((r)[18]), "r"((r)[19]), \
           "r"((r)[20]), "r"((r)[21]), "r"((r)[22]), "r"((r)[23]), \
           "r"((r)[24]), "r"((r)[25]), "r"((r)[26]), "r"((r)[27]), \
           "r"((r)[28]), "r"((r)[29]), "r"((r)[30]), "r"((r)[31]) \
        : "memory")
#endif  // TC_OK

// ===========================================================================
// Precision-split conversion:  x = hi(bf16) + lo(bf16), lo exact residual.
// ===========================================================================
__global__ __launch_bounds__(256) void convert_hilo(
    const float* __restrict__ in, __nv_bfloat16* __restrict__ hi,
    __nv_bfloat16* __restrict__ lo, int n4)
{
    int i = blockIdx.x * blockDim.x + threadIdx.x;
    if (i >= n4) return;
    float4 v = ((const float4*)in)[i];
    float vv[4] = {v.x, v.y, v.z, v.w};
    union { __nv_bfloat162 b2[2]; uint2 u; } uh, ul;
#pragma unroll
    for (int e = 0; e < 4; e += 2) {
        __nv_bfloat16 h0 = __float2bfloat16(vv[e]);
        __nv_bfloat16 h1 = __float2bfloat16(vv[e + 1]);
        __nv_bfloat16 l0 = __float2bfloat16(vv[e]     - __bfloat162float(h0));
        __nv_bfloat16 l1 = __float2bfloat16(vv[e + 1] - __bfloat162float(h1));
        uh.b2[e >> 1] = __nv_bfloat162(h0, h1);
        ul.b2[e >> 1] = __nv_bfloat162(l0, l1);
    }
    ((uint2*)hi)[i] = uh.u;
    ((uint2*)lo)[i] = ul.u;
}

// W [K,N] fp32  ->  Wt_hi/lo [N,K] bf16  (transpose + split)
__global__ __launch_bounds__(256) void transpose_convert(
    const float* __restrict__ w, __nv_bfloat16* __restrict__ thi,
    __nv_bfloat16* __restrict__ tlo, int Kdim, int Ndim)
{
    __shared__ float tile[32][33];
    const int nb = blockIdx.x * 32, kb = blockIdx.y * 32;
    const int tx = threadIdx.x, ty = threadIdx.y;   // 32 x 8
#pragma unroll
    for (int i = 0; i < 32; i += 8)
        tile[ty + i][tx] = w[(size_t)(kb + ty + i) * Ndim + nb + tx];
    __syncthreads();
#pragma unroll
    for (int i = 0; i < 32; i += 8) {
        float x = tile[tx][ty + i];
        __nv_bfloat16 h = __float2bfloat16(x);
        __nv_bfloat16 l = __float2bfloat16(x - __bfloat162float(h));
        size_t o = (size_t)(nb + ty + i) * Kdim + kb + tx;
        thi[o] = h;  tlo[o] = l;
    }
}

// ===========================================================================
// tcgen05 GEMM — TS mode, REGISTER-PREFETCH pipeline, 256 threads.
// The tcgen05/mbarrier protocol is byte-identical to the R12 PASSING kernel:
// single B SMEM buffer, single A TMEM staging, per chunk:
//   store staged regs -> SMEM/TMEM; fence; sync; warp0-elect MMAs + commit;
//   next iteration's head waits parity (c-1)&1 before overwriting.
// The ONLY addition: global loads for chunk c+1 are issued into registers
// BEFORE the MMA/wait, so LDG latency overlaps MMA execution. No concurrent
// TMEM/SMEM writes during in-flight MMAs ever occur.
// Work split: warpgroup 0 stages A (1 row/thread, 64 regs); warpgroup 1
// loads B hi/lo (16 uint4/thread). TMEM: D=0..127, AH=128..159, AL=160..191
// (alloc 256); 2 CTAs/SM by SMEM pad (98KB) -> 512 TMEM cols total.
// ===========================================================================
#define GT_KC     64
#define GT_TILEB  (128 * 128)            // 16 KB per B tile
#define GT_SMEM   (98 * 1024)            // padded: cap 2 CTAs/SM
// idesc kind::f16: dtype=F32, a/b=BF16, N=128, M=128 (test_mma field layout)
#define GT_IDESC  ((1u<<4) | (1u<<7) | (1u<<10) | ((128u/8u)<<17) | ((128u/16u)<<24))

__global__ __launch_bounds__(256, 1)
void gemm_tc(const __nv_bfloat16* __restrict__ Ahi,
             const __nv_bfloat16* __restrict__ Alo,
             const __nv_bfloat16* __restrict__ Bhi,
             const __nv_bfloat16* __restrict__ Blo,
             const float* __restrict__ bias, float* __restrict__ C,
             int Mdim, int Ndim, int Kdim)
{
#if TC_OK
    extern __shared__ unsigned char smem[];
    const uint32_t smem_base = smem_u32(smem);
    const int tid  = threadIdx.x;       // 0..255
    const int wid  = tid >> 5;
    const int lane = tid & 31;
    const int wg   = tid >> 7;          // 0: A-staging, 1: B-loading
    const int wg_tid = tid & 127;
    const int brow = blockIdx.y * 128;
    const int bcol = blockIdx.x * 128;
    const int NC   = Kdim / GT_KC;

    if (wid == 0) TC_ALLOC(smem_base, 256);
    if (tid == 0) mbar_init(smem_base + 8, 1);
    __syncthreads();
    uint32_t tmem_base;
    asm volatile("ld.shared.b32 %0, [%1];" : "=r"(tmem_base) : "r"(smem_base));

    const uint32_t TD  = tmem_base;        // D: 128 cols
    const uint32_t TAH = tmem_base + 128;  // A hi: 32 cols
    const uint32_t TAL = tmem_base + 160;  // A lo: 32 cols
    const uint64_t dBH = mk_sw128_desc(smem_base + 1024);
    const uint64_t dBL = mk_sw128_desc(smem_base + 1024 + GT_TILEB);
    const uint32_t woff = ((uint32_t)wg_tid >> 5) << 21;

    // prefetch registers
    uint32_t a_hi[32], a_lo[32];   // warpgroup 0
    uint4    bq[16];               // warpgroup 1 (2 tiles x 8 uint4)

    // ---- register prefetch of chunk c ------------------------------------
    auto load_regs = [&](int c) {
        const int k0 = c * GT_KC;
        if (wg == 1) {
#pragma unroll
            for (int t = 0; t < 2; t++) {
                const __nv_bfloat16* s = t ? Blo : Bhi;
#pragma unroll
                for (int e = 0; e < 8; e++) {
                    const int i  = wg_tid + e * 128;
                    const int r  = i >> 3;
                    const int kq = i & 7;
                    bq[t * 8 + e] =
                        *(const uint4*)(s + (size_t)(bcol + r) * Kdim + k0 + kq * 8);
                }
            }
        } else {
            const uint4* ph = (const uint4*)(Ahi + (size_t)(brow + wg_tid) * Kdim + k0);
            const uint4* pl = (const uint4*)(Alo + (size_t)(brow + wg_tid) * Kdim + k0);
#pragma unroll
            for (int e = 0; e < 8; e++) {
                uint4 vh = ph[e];
                a_hi[e * 4 + 0] = vh.x; a_hi[e * 4 + 1] = vh.y;
                a_hi[e * 4 + 2] = vh.z; a_hi[e * 4 + 3] = vh.w;
                uint4 vl = pl[e];
                a_lo[e * 4 + 0] = vl.x; a_lo[e * 4 + 1] = vl.y;
                a_lo[e * 4 + 2] = vl.z; a_lo[e * 4 + 3] = vl.w;
            }
        }
    };

    load_regs(0);

    for (int c = 0; c < NC; c++) {
        // wait for chunk c-1's MMAs before overwriting staged operands
        if (c > 0) mbar_wait(smem_base + 8, (uint32_t)((c - 1) & 1));

        // ---- commit staged registers to SMEM / TMEM ------------------------
        if (wg == 1) {
#pragma unroll
            for (int t = 0; t < 2; t++) {
                unsigned char* dst = smem + 1024 + t * GT_TILEB;
#pragma unroll
                for (int e = 0; e < 8; e++) {
                    const int i  = wg_tid + e * 128;
                    const int r  = i >> 3;
                    const int kq = i & 7;
                    uint32_t off = r * 128 + kq * 16;
                    off ^= (off >> 3) & 0x70;        // SW128 swizzle
                    *(uint4*)(dst + off) = bq[t * 8 + e];
                }
            }
        } else {
            TCST32(TAH + woff, a_hi);
            TCST32(TAL + woff, a_lo);
            TC_WAIT_ST();
        }

        // ---- issue LDGs for next chunk (latency overlaps MMA below) --------
        if (c + 1 < NC) load_regs(c + 1);

        TC_FENCE_BEFORE();
        FENCE_PROXY_ASYNC();
        __syncthreads();

        // ---- MMA issue: warp 0, elected thread (R12-identical envelope) ----
        if (wid == 0) {
            TC_FENCE_AFTER();
            if (elect_one()) {
#pragma unroll
                for (int ksub = 0; ksub < 4; ksub++) {
                    const uint64_t o  = ksub * 2;   // B: 16 bf16 = 2 units
                    const uint32_t ac = ksub * 8;   // A: 16 bf16 = 8 TMEM cols
                    uint32_t en0 = (c == 0 && ksub == 0) ? 0u : 1u;
                    tc_mma_f16_ts(TD, TAH + ac, dBH + o, GT_IDESC, en0);
                    tc_mma_f16_ts(TD, TAH + ac, dBL + o, GT_IDESC, 1u);
                    tc_mma_f16_ts(TD, TAL + ac, dBH + o, GT_IDESC, 1u);
                }
                tc_commit(smem_base + 8);
            }
        }
        __syncthreads();
    }

    // final drain
    mbar_wait(smem_base + 8, (uint32_t)((NC - 1) & 1));
    __syncthreads();
    TC_FENCE_AFTER();

    // epilogue: 8 warps; warps 0-3 cols 0..63, warps 4-7 cols 64..127
    {
        const int r = (wid & 3) * 32 + lane;
        const int colbase = (wid >> 2) * 64;
        float* crow = C + (size_t)(brow + r) * Ndim + bcol;
#pragma unroll
        for (int cb = 0; cb < 2; cb++) {
            uint32_t dreg[32];
            TCLD32(dreg, TD + colbase + cb * 32);
            TC_WAIT_LD();
#pragma unroll
            for (int j = 0; j < 32; j += 4) {
                const int col = colbase + cb * 32 + j;
                float4 o;
                o.x = __uint_as_float(dreg[j + 0]) + bias[bcol + col + 0];
                o.y = __uint_as_float(dreg[j + 1]) + bias[bcol + col + 1];
                o.z = __uint_as_float(dreg[j + 2]) + bias[bcol + col + 2];
                o.w = __uint_as_float(dreg[j + 3]) + bias[bcol + col + 3];
                *(float4*)(crow + col) = o;
            }
        }
        TC_FENCE_BEFORE();
    }
    __syncthreads();
    if (wid == 0) TC_DEALLOC(tmem_base, 256);

#else  // -------- portable fallback (non-'a' PTX pass only; never runs) -----
    const int tid  = threadIdx.x;
    const int brow = blockIdx.y * 128;
    const int bcol = blockIdx.x * 128;
    const int r = brow + (tid & 127);
    const int ch = (tid >> 7) * 64;       // column half
    for (int c0 = ch; c0 < ch + 64; c0 += 8) {
        float acc[8];
#pragma unroll
        for (int j = 0; j < 8; j++) acc[j] = 0.0f;
        for (int kk = 0; kk < Kdim; kk++) {
            float a = __bfloat162float(Ahi[(size_t)r * Kdim + kk])
                    + __bfloat162float(Alo[(size_t)r * Kdim + kk]);
#pragma unroll
            for (int j = 0; j < 8; j++) {
                const int cc = bcol + c0 + j;
                float b = __bfloat162float(Bhi[(size_t)cc * Kdim + kk])
                        + __bfloat162float(Blo[(size_t)cc * Kdim + kk]);
                acc[j] = fmaf(a, b, acc[j]);
            }
        }
#pragma unroll
        for (int j = 0; j < 8; j++)
            C[(size_t)r * Ndim + bcol + c0 + j] = acc[j] + bias[bcol + c0 + j];
    }
#endif
}

// ---------------------------------------------------------------------------
// Fused interleave-to-half + RoPE
// ---------------------------------------------------------------------------
__global__ __launch_bounds__(256) void rope_kernel(float* __restrict__ t,
                                                   int total_heads, int nh)
{
    const int gw = (blockIdx.x * blockDim.x + threadIdx.x) >> 5;
    if (gw >= total_heads) return;
    const int lane = threadIdx.x & 31;
    const int s = (gw / nh) % S_;

    float* base = t + (size_t)gw * 128;
    float e0 = base[2 * lane],      o0 = base[2 * lane + 1];
    float e1 = base[2 * lane + 64], o1 = base[2 * lane + 65];
    __syncwarp();

    const float pos = (float)s;
    const float f0 = powf(10000.0f, -((float)lane) / 64.0f);
    const float f1 = powf(10000.0f, -((float)(lane + 32)) / 64.0f);
    float s0, c0, s1, c1;
    sincosf(pos * f0, &s0, &c0);
    sincosf(pos * f1, &s1, &c1);

    base[lane]      = e0 * c0 - o0 * s0;
    base[lane + 64] = e0 * s0 + o0 * c0;
    base[lane + 32] = e1 * c1 - o1 * s1;
    base[lane + 96] = e1 * s1 + o1 * c1;
}

// ---------------------------------------------------------------------------
// Causal flash attention, fp32. Softmax: 4 threads/row, shfl width-4 reduce.
// ---------------------------------------------------------------------------
#define FA_SMEM_FLOATS (128*64 + 128*64 + 64*128 + 64*68 + 3*64)

__global__ __launch_bounds__(256) void flash_kernel(
    const float* __restrict__ q, const float* __restrict__ k,
    const float* __restrict__ v, float* __restrict__ ctx)
{
    extern __shared__ float sm[];
    float* Qs  = sm;
    float* Ks  = Qs + 128 * 64;
    float* Vs  = Ks + 128 * 64;
    float* Ss  = Vs + 64 * 128;
    float* mrow = Ss + 64 * 68;
    float* lrow = mrow + 64;
    float* arow = lrow + 64;

    const int tid = threadIdx.x;
    const int qt  = blockIdx.x;
    const int bh  = blockIdx.y;
    const int b   = bh >> 5;
    const int h   = bh & 31;
    const int hkv = h >> 2;

    const float* qbase = q + ((size_t)(b * S_ + qt * 64) * H_ + h) * D_;
    const float* kbase = k + ((size_t)(b * S_) * HKV_ + hkv) * D_;
    const float* vbase = v + ((size_t)(b * S_) * HKV_ + hkv) * D_;

    const int tq = tid >> 4;
    const int tk = tid & 15;
    const int srow = tid >> 2;       // softmax: row 0..63
    const int squad = tid & 3;       // 4 threads per row, 16 cols each

    for (int idx = tid; idx < 64 * 32; idx += 256) {
        const int row = idx & 63;
        const int dq  = idx >> 6;
        float4 val = *(const float4*)(qbase + (size_t)row * (H_ * D_) + dq * 4);
        Qs[(dq * 4 + 0) * 64 + row] = val.x;
        Qs[(dq * 4 + 1) * 64 + row] = val.y;
        Qs[(dq * 4 + 2) * 64 + row] = val.z;
        Qs[(dq * 4 + 3) * 64 + row] = val.w;
    }
    if (tid < 64) { mrow[tid] = -INFINITY; lrow[tid] = 0.0f; }

    float o[4][8];
#pragma unroll
    for (int i = 0; i < 4; i++)
#pragma unroll
        for (int j = 0; j < 8; j++) o[i][j] = 0.0f;

    const float scale = 0.08838834764831845f;

    for (int jt = 0; jt <= qt; jt++) {
        __syncthreads();

        const float* ktile = kbase + (size_t)(jt * 64) * (HKV_ * D_);
        for (int idx = tid; idx < 64 * 32; idx += 256) {
            const int kk = idx & 63;
            const int dq = idx >> 6;
            float4 val = *(const float4*)(ktile + (size_t)kk * (HKV_ * D_) + dq * 4);
            Ks[(dq * 4 + 0) * 64 + kk] = val.x;
            Ks[(dq * 4 + 1) * 64 + kk] = val.y;
            Ks[(dq * 4 + 2) * 64 + kk] = val.z;
            Ks[(dq * 4 + 3) * 64 + kk] = val.w;
        }
        const float* vtile = vbase + (size_t)(jt * 64) * (HKV_ * D_);
        for (int idx = tid; idx < 64 * 32; idx += 256) {
            const int dq = idx & 31;
            const int kk = idx >> 5;
            *(float4*)(&Vs[kk * 128 + dq * 4]) =
                *(const float4*)(vtile + (size_t)kk * (HKV_ * D_) + dq * 4);
        }
        __syncthreads();

        float accS[4][4];
#pragma unroll
        for (int i = 0; i < 4; i++)
#pragma unroll
            for (int j = 0; j < 4; j++) accS[i][j] = 0.0f;

#pragma unroll 4
        for (int kd = 0; kd < 128; kd++) {
            float4 aq = *(float4*)(&Qs[kd * 64 + tq * 4]);
            float4 bk = *(float4*)(&Ks[kd * 64 + tk * 4]);
            float ar[4] = {aq.x, aq.y, aq.z, aq.w};
            float br[4] = {bk.x, bk.y, bk.z, bk.w};
#pragma unroll
            for (int i = 0; i < 4; i++)
#pragma unroll
                for (int j = 0; j < 4; j++)
                    accS[i][j] = fmaf(ar[i], br[j], accS[i][j]);
        }

        const int qg0 = qt * 64 + tq * 4;
        const int kg0 = jt * 64 + tk * 4;
#pragma unroll
        for (int i = 0; i < 4; i++) {
#pragma unroll
            for (int j = 0; j < 4; j++) {
                float sv = accS[i][j] * scale;
                if (jt == qt && (kg0 + j) > (qg0 + i)) sv = -1e30f;
                Ss[(tq * 4 + i) * 68 + tk * 4 + j] = sv;
            }
        }
        __syncthreads();

        // ---- online softmax: 4 threads per row, shfl width-4 reductions ----
        {
            const float mold = mrow[srow];
            float mx = mold;
            const int c0 = squad * 16;
#pragma unroll
            for (int cc = 0; cc < 16; cc++)
                mx = fmaxf(mx, Ss[srow * 68 + c0 + cc]);
            mx = fmaxf(mx, __shfl_xor_sync(0xffffffffu, mx, 1));
            mx = fmaxf(mx, __shfl_xor_sync(0xffffffffu, mx, 2));
            float sum = 0.0f;
#pragma unroll
            for (int cc = 0; cc < 16; cc++) {
                float p = expf(Ss[srow * 68 + c0 + cc] - mx);
                Ss[srow * 68 + c0 + cc] = p;
                sum += p;
            }
            sum += __shfl_xor_sync(0xffffffffu, sum, 1);
            sum += __shfl_xor_sync(0xffffffffu, sum, 2);
            if (squad == 0) {
                const float alpha = expf(mold - mx);
                lrow[srow] = lrow[srow] * alpha + sum;
                mrow[srow] = mx;
                arow[srow] = alpha;
            }
        }
        __syncthreads();

        float alr[4];
#pragma unroll
        for (int i = 0; i < 4; i++) alr[i] = arow[tq * 4 + i];
#pragma unroll
        for (int i = 0; i < 4; i++)
#pragma unroll
            for (int j = 0; j < 8; j++) o[i][j] *= alr[i];

#pragma unroll 2
        for (int kk = 0; kk < 64; kk++) {
            float4 v0 = *(float4*)(&Vs[kk * 128 + tk * 8]);
            float4 v1 = *(float4*)(&Vs[kk * 128 + tk * 8 + 4]);
#pragma unroll
            for (int i = 0; i < 4; i++) {
                float p = Ss[(tq * 4 + i) * 68 + kk];
                o[i][0] = fmaf(p, v0.x, o[i][0]);
                o[i][1] = fmaf(p, v0.y, o[i][1]);
                o[i][2] = fmaf(p, v0.z, o[i][2]);
                o[i][3] = fmaf(p, v0.w, o[i][3]);
                o[i][4] = fmaf(p, v1.x, o[i][4]);
                o[i][5] = fmaf(p, v1.y, o[i][5]);
                o[i][6] = fmaf(p, v1.z, o[i][6]);
                o[i][7] = fmaf(p, v1.w, o[i][7]);
            }
        }
    }
    __syncthreads();

#pragma unroll
    for (int i = 0; i < 4; i++) {
        const float inv = 1.0f / lrow[tq * 4 + i];
        const int qg = qt * 64 + tq * 4 + i;
        float* outp = ctx + ((size_t)(b * S_ + qg) * H_ + h) * D_ + tk * 8;
        float4 w0, w1;
        w0.x = o[i][0] * inv; w0.y = o[i][1] * inv;
        w0.z = o[i][2] * inv; w0.w = o[i][3] * inv;
        w1.x = o[i][4] * inv; w1.y = o[i][5] * inv;
        w1.z = o[i][6] * inv; w1.w = o[i][7] * inv;
        *(float4*)(outp)     = w0;
        *(float4*)(outp + 4) = w1;
    }
}

// ---------------------------------------------------------------------------
extern "C" void kernel_launch(void* const* d_in, const int* in_sizes, int n_in,
                              void* d_out, int out_size)
{
    const float* x    = (const float*)d_in[0];
    const float* wq_w = (const float*)d_in[1];
    const float* wq_b = (const float*)d_in[2];
    const float* wk_w = (const float*)d_in[3];
    const float* wk_b = (const float*)d_in[4];
    const float* wv_w = (const float*)d_in[5];
    const float* wv_b = (const float*)d_in[6];
    const float* wo_w = (const float*)d_in[7];
    const float* wo_b = (const float*)d_in[8];

    float *q, *k, *v, *ctx;
    __nv_bfloat16 *ahi, *alo, *wqh, *wql, *wkh, *wkl, *wvh, *wvl, *woh, *wol;
    cudaGetSymbolAddress((void**)&q,   g_q);
    cudaGetSymbolAddress((void**)&k,   g_k);
    cudaGetSymbolAddress((void**)&v,   g_v);
    cudaGetSymbolAddress((void**)&ctx, g_ctx);
    cudaGetSymbolAddress((void**)&ahi, g_ahi);
    cudaGetSymbolAddress((void**)&alo, g_alo);
    cudaGetSymbolAddress((void**)&wqh, g_wqt_hi);
    cudaGetSymbolAddress((void**)&wql, g_wqt_lo);
    cudaGetSymbolAddress((void**)&wkh, g_wkt_hi);
    cudaGetSymbolAddress((void**)&wkl, g_wkt_lo);
    cudaGetSymbolAddress((void**)&wvh, g_wvt_hi);
    cudaGetSymbolAddress((void**)&wvl, g_wvt_lo);
    cudaGetSymbolAddress((void**)&woh, g_wot_hi);
    cudaGetSymbolAddress((void**)&wol, g_wot_lo);

    cudaFuncSetAttribute(gemm_tc, cudaFuncAttributeMaxDynamicSharedMemorySize, GT_SMEM);
    cudaFuncSetAttribute(flash_kernel, cudaFuncAttributeMaxDynamicSharedMemorySize,
                         FA_SMEM_FLOATS * (int)sizeof(float));

    const dim3 tb(32, 8);
    // weight transpose + bf16 split (one pass over the weights)
    transpose_convert<<<dim3(E_ / 32,   E_ / 32), tb>>>(wq_w, wqh, wql, E_, E_);
    transpose_convert<<<dim3(NKV_ / 32, E_ / 32), tb>>>(wk_w, wkh, wkl, E_, NKV_);
    transpose_convert<<<dim3(NKV_ / 32, E_ / 32), tb>>>(wv_w, wvh, wvl, E_, NKV_);
    transpose_convert<<<dim3(E_ / 32,   E_ / 32), tb>>>(wo_w, woh, wol, E_, E_);
    // activation split
    convert_hilo<<<(M_ * E_ / 4) / 256, 256>>>(x, ahi, alo, M_ * E_ / 4);

    // QKV projections on tcgen05 (TS mode, register-prefetch pipeline)
    gemm_tc<<<dim3(E_ / 128,   M_ / 128), 256, GT_SMEM>>>(ahi, alo, wqh, wql, wq_b, q, M_, E_,   E_);
    gemm_tc<<<dim3(NKV_ / 128, M_ / 128), 256, GT_SMEM>>>(ahi, alo, wkh, wkl, wk_b, k, M_, NKV_, E_);
    gemm_tc<<<dim3(NKV_ / 128, M_ / 128), 256, GT_SMEM>>>(ahi, alo, wvh, wvl, wv_b, v, M_, NKV_, E_);

    // RoPE on q and k (in place)
    rope_kernel<<<(M_ * H_   * 32) / 256, 256>>>(q, M_ * H_,   H_);
    rope_kernel<<<(M_ * HKV_ * 32) / 256, 256>>>(k, M_ * HKV_, HKV_);

    // Flash attention (fp32)
    const int fa_smem = FA_SMEM_FLOATS * (int)sizeof(float);
    flash_kernel<<<dim3(32, 64), 256, fa_smem>>>(q, k, v, ctx);

    // Output projection on tcgen05
    convert_hilo<<<(M_ * E_ / 4) / 256, 256>>>(ctx, ahi, alo, M_ * E_ / 4);
    gemm_tc<<<dim3(E_ / 128, M_ / 128), 256, GT_SMEM>>>(ahi, alo, woh, wol, wo_b,
                                                        (float*)d_out, M_, E_, E_);
}

// round 17
// speedup vs baseline: 4.2939x; 1.7463x over previous
#include <cuda_runtime.h>
#include <cuda_bf16.h>
#include <math.h>
#include <stdint.h>

#define B_   2
#define S_   2048
#define E_   4096
#define H_   32
#define HKV_ 8
#define D_   128
#define M_   (B_*S_)   // 4096 tokens
#define NKV_ (HKV_*D_) // 1024

// ---- arch gate: tcgen05 only exists on the arch-specific ('a') target -----
#ifndef __CUDA_ARCH_HAS_FEATURE__
#define __CUDA_ARCH_HAS_FEATURE__(x) 0
#endif
#if defined(__CUDA_ARCH__)
#  if __CUDA_ARCH_HAS_FEATURE__(SM103_ALL) || __CUDA_ARCH_HAS_FEATURE__(SM100_ALL) || \
      __CUDA_ARCH_HAS_FEATURE__(SM101_ALL) || defined(__CUDA_ARCH_SPECIFIC__)
#    define TC_OK 1
#  else
#    define TC_OK 0
#  endif
#else
#  define TC_OK 0
#endif

// ---------------- scratch (device globals; no allocation allowed) ----------
__device__ float g_q[M_ * E_];
__device__ float g_k[M_ * NKV_];
__device__ float g_v[M_ * NKV_];
__device__ float g_ctx[M_ * E_];
// bf16 hi/lo split scratch
__device__ __nv_bfloat16 g_ahi[M_ * E_];     // x-split, later q-split, later ctx-split
__device__ __nv_bfloat16 g_alo[M_ * E_];
__device__ __nv_bfloat16 g_khi[M_ * NKV_];
__device__ __nv_bfloat16 g_klo[M_ * NKV_];
__device__ __nv_bfloat16 g_vthi[M_ * NKV_];  // V^T: [b, hkv, d, s]
__device__ __nv_bfloat16 g_vtlo[M_ * NKV_];
__device__ __nv_bfloat16 g_wqt_hi[E_ * E_];
__device__ __nv_bfloat16 g_wqt_lo[E_ * E_];
__device__ __nv_bfloat16 g_wkt_hi[NKV_ * E_];
__device__ __nv_bfloat16 g_wkt_lo[NKV_ * E_];
__device__ __nv_bfloat16 g_wvt_hi[NKV_ * E_];
__device__ __nv_bfloat16 g_wvt_lo[NKV_ * E_];
__device__ __nv_bfloat16 g_wot_hi[E_ * E_];
__device__ __nv_bfloat16 g_wot_lo[E_ * E_];

// =================== PTX helpers (guarded, sm_103a only) ====================
#if TC_OK
__device__ __forceinline__ uint32_t smem_u32(const void* p) {
    uint32_t a;
    asm("{ .reg .u64 t; cvta.to.shared.u64 t, %1; cvt.u32.u64 %0, t; }"
        : "=r"(a) : "l"(p));
    return a;
}
__device__ __forceinline__ uint32_t elect_one() {
    uint32_t pred;
    asm volatile(
        "{\n\t.reg .pred p;\n\t"
        "elect.sync _|p, 0xFFFFFFFF;\n\t"
        "selp.b32 %0, 1, 0, p;\n\t}"
        : "=r"(pred));
    return pred;
}
__device__ __forceinline__ uint64_t mk_sw128_desc(uint32_t addr) {
    const uint64_t BASE = (uint64_t(2) << 61)   // SW128
                        | (uint64_t(1) << 46)   // version=1 (Blackwell)
                        | (uint64_t(64) << 32)  // SBO = 64
                        | (uint64_t(1) << 16);  // LBO = 1
    return BASE | ((addr >> 4) & 0x3FFF);
}
// TS-mode f16 MMA: A in TMEM, B in SMEM (validated: test_mma[_iter].cu + R14)
__device__ __forceinline__ void tc_mma_f16_ts(uint32_t d, uint32_t a_tmem,
                                              uint64_t bd, uint32_t idesc,
                                              uint32_t en) {
    asm volatile(
        "{\n\t.reg .pred p;\n\tsetp.ne.u32 p, %4, 0;\n\t"
        "tcgen05.mma.cta_group::1.kind::f16 [%0], [%1], %2, %3, {%5,%5,%5,%5}, p;\n\t}"
        :: "r"(d), "r"(a_tmem), "l"(bd), "r"(idesc), "r"(en), "r"(0u) : "memory");
}
__device__ __forceinline__ void tc_commit(uint32_t mbar) {
    asm volatile(
        "tcgen05.commit.cta_group::1.mbarrier::arrive::one.shared::cluster.b64 [%0];"
        :: "r"(mbar) : "memory");
}
__device__ __forceinline__ void mbar_init(uint32_t a, uint32_t cnt) {
    asm volatile("mbarrier.init.shared.b64 [%0], %1;" :: "r"(a), "r"(cnt) : "memory");
}
__device__ __forceinline__ void mbar_wait(uint32_t a, uint32_t parity) {
    uint32_t done;
    asm volatile(
        "{\n\t.reg .pred p;\n\t"
        "mbarrier.try_wait.parity.acquire.cta.shared::cta.b64 p, [%1], %2;\n\t"
        "selp.b32 %0, 1, 0, p;\n\t}"
        : "=r"(done) : "r"(a), "r"(parity) : "memory");
    if (!done) {
        asm volatile(
            "{\n\t.reg .pred P1;\n\t"
            "WAIT_LOOP_%=:\n\t"
            "mbarrier.try_wait.parity.acquire.cta.shared::cta.b64 P1, [%0], %1, 0x989680;\n\t"
            "@P1 bra.uni WAIT_DONE_%=;\n\t"
            "bra.uni WAIT_LOOP_%=;\n\t"
            "WAIT_DONE_%=:\n\t}"
            :: "r"(a), "r"(parity) : "memory");
    }
}
#define TC_ALLOC(sm, n)   asm volatile("tcgen05.alloc.cta_group::1.sync.aligned.shared::cta.b32 [%0], %1;" :: "r"(sm), "r"((uint32_t)(n)) : "memory")
#define TC_DEALLOC(t, n)  asm volatile("tcgen05.dealloc.cta_group::1.sync.aligned.b32 %0, %1;" :: "r"(t), "r"((uint32_t)(n)))
#define TC_FENCE_AFTER()  asm volatile("tcgen05.fence::after_thread_sync;" ::: "memory")
#define TC_FENCE_BEFORE() asm volatile("tcgen05.fence::before_thread_sync;" ::: "memory")
#define TC_WAIT_LD()      asm volatile("tcgen05.wait::ld.sync.aligned;" ::: "memory")
#define TC_WAIT_ST()      asm volatile("tcgen05.wait::st.sync.aligned;" ::: "memory")
#define FENCE_PROXY_ASYNC() asm volatile("fence.proxy.async.shared::cta;" ::: "memory")

#define TCLD32(r, ta) \
    asm volatile( \
        "tcgen05.ld.sync.aligned.32x32b.x32.b32 " \
        "{%0, %1, %2, %3, %4, %5, %6, %7, " \
        " %8, %9, %10, %11, %12, %13, %14, %15, " \
        " %16, %17, %18, %19, %20, %21, %22, %23, " \
        " %24, %25, %26, %27, %28, %29, %30, %31}, [%32];" \
        : "=r"((r)[0]),  "=r"((r)[1]),  "=r"((r)[2]),  "=r"((r)[3]), \
          "=r"((r)[4]),  "=r"((r)[5]),  "=r"((r)[6]),  "=r"((r)[7]), \
          "=r"((r)[8]),  "=r"((r)[9]),  "=r"((r)[10]), "=r"((r)[11]), \
          "=r"((r)[12]), "=r"((r)[13]), "=r"((r)[14]), "=r"((r)[15]), \
          "=r"((r)[16]), "=r"((r)[17]), "=r"((r)[18]), "=r"((r)[19]), \
          "=r"((r)[20]), "=r"((r)[21]), "=r"((r)[22]), "=r"((r)[23]), \
          "=r"((r)[24]), "=r"((r)[25]), "=r"((r)[26]), "=r"((r)[27]), \
          "=r"((r)[28]), "=r"((r)[29]), "=r"((r)[30]), "=r"((r)[31]) \
        : "r"(ta))

#define TCST32(ta, r) \
    asm volatile( \
        "tcgen05.st.sync.aligned.32x32b.x32.b32 [%0], " \
        "{%1, %2, %3, %4, %5, %6, %7, %8, " \
        " %9, %10, %11, %12, %13, %14, %15, %16, " \
        " %17, %18, %19, %20, %21, %22, %23, %24, " \
        " %25, %26, %27, %28, %29, %30, %31, %32};" \
        :: "r"(ta), \
           "r"((r)[0]),  "r"((r)[1]),  "r"((r)[2]),  "r"((r)[3]), \
           "r"((r)[4]),  "r"((r)[5]),  "r"((r)[6]),  "r"((r)[7]), \
           "r"((r)[8]),  "r"((r)[9]),  "r"((r)[10]), "r"((r)[11]), \
           "r"((r)[12]), "r"((r)[13]), "r"((r)[14]), "r"((r)[15]), \
           "r"((r)[16]), "r"((r)[17]), "r"((r)[18]), "r"((r)[19]), \
           "r"((r)[20]), "r"((r)[21]), "r"((r)[22]), "r"((r)[23]), \
           "r"((r)[24]), "r"((r)[25]), "r"((r)[26]), "r"((r)[27]), \
           "r"((r)[28]), "r"((r)[29]), "r"((r)[30]), "r"((r)[31]) \
        : "memory")
#endif  // TC_OK

// ===========================================================================
// Precision-split conversion:  x = hi(bf16) + lo(bf16), lo exact residual.
// ===========================================================================
__global__ __launch_bounds__(256) void convert_hilo(
    const float* __restrict__ in, __nv_bfloat16* __restrict__ hi,
    __nv_bfloat16* __restrict__ lo, int n4)
{
    int i = blockIdx.x * blockDim.x + threadIdx.x;
    if (i >= n4) return;
    float4 v = ((const float4*)in)[i];
    float vv[4] = {v.x, v.y, v.z, v.w};
    union { __nv_bfloat162 b2[2]; uint2 u; } uh, ul;
#pragma unroll
    for (int e = 0; e < 4; e += 2) {
        __nv_bfloat16 h0 = __float2bfloat16(vv[e]);
        __nv_bfloat16 h1 = __float2bfloat16(vv[e + 1]);
        __nv_bfloat16 l0 = __float2bfloat16(vv[e]     - __bfloat162float(h0));
        __nv_bfloat16 l1 = __float2bfloat16(vv[e + 1] - __bfloat162float(h1));
        uh.b2[e >> 1] = __nv_bfloat162(h0, h1);
        ul.b2[e >> 1] = __nv_bfloat162(l0, l1);
    }
    ((uint2*)hi)[i] = uh.u;
    ((uint2*)lo)[i] = ul.u;
}

// W [K,N] fp32  ->  Wt_hi/lo [N,K] bf16  (transpose + split)
__global__ __launch_bounds__(256) void transpose_convert(
    const float* __restrict__ w, __nv_bfloat16* __restrict__ thi,
    __nv_bfloat16* __restrict__ tlo, int Kdim, int Ndim)
{
    __shared__ float tile[32][33];
    const int nb = blockIdx.x * 32, kb = blockIdx.y * 32;
    const int tx = threadIdx.x, ty = threadIdx.y;   // 32 x 8
#pragma unroll
    for (int i = 0; i < 32; i += 8)
        tile[ty + i][tx] = w[(size_t)(kb + ty + i) * Ndim + nb + tx];
    __syncthreads();
#pragma unroll
    for (int i = 0; i < 32; i += 8) {
        float x = tile[tx][ty + i];
        __nv_bfloat16 h = __float2bfloat16(x);
        __nv_bfloat16 l = __float2bfloat16(x - __bfloat162float(h));
        size_t o = (size_t)(nb + ty + i) * Kdim + kb + tx;
        thi[o] = h;  tlo[o] = l;
    }
}

// V [b,s,hkv,d] fp32 -> Vt hi/lo [b,hkv,d,s] bf16  (per-head transpose+split)
__global__ __launch_bounds__(256) void vtrans_convert(
    const float* __restrict__ v, __nv_bfloat16* __restrict__ vthi,
    __nv_bfloat16* __restrict__ vtlo)
{
    __shared__ float tile[32][33];
    const int bhkv = blockIdx.z;
    const int b = bhkv >> 3, hkv = bhkv & 7;
    const int s0 = blockIdx.x * 32, d0 = blockIdx.y * 32;
    const int tx = threadIdx.x, ty = threadIdx.y;   // 32 x 8
#pragma unroll
    for (int i = 0; i < 32; i += 8)
        tile[ty + i][tx] =
            v[((size_t)(b * S_ + s0 + ty + i) * HKV_ + hkv) * D_ + d0 + tx];
    __syncthreads();
#pragma unroll
    for (int i = 0; i < 32; i += 8) {
        float x = tile[tx][ty + i];
        __nv_bfloat16 h = __float2bfloat16(x);
        __nv_bfloat16 l = __float2bfloat16(x - __bfloat162float(h));
        size_t o = ((size_t)(b * HKV_ + hkv) * D_ + d0 + ty + i) * S_ + s0 + tx;
        vthi[o] = h;  vtlo[o] = l;
    }
}

// ===========================================================================
// tcgen05 GEMM — TS mode, REGISTER-PREFETCH pipeline (UNCHANGED from R14 WIN).
// ===========================================================================
#define GT_KC     64
#define GT_TILEB  (128 * 128)            // 16 KB per B tile
#define GT_SMEM   (98 * 1024)            // padded: cap 2 CTAs/SM
#define GT_IDESC  ((1u<<4) | (1u<<7) | (1u<<10) | ((128u/8u)<<17) | ((128u/16u)<<24))

__global__ __launch_bounds__(256, 1)
void gemm_tc(const __nv_bfloat16* __restrict__ Ahi,
             const __nv_bfloat16* __restrict__ Alo,
             const __nv_bfloat16* __restrict__ Bhi,
             const __nv_bfloat16* __restrict__ Blo,
             const float* __restrict__ bias, float* __restrict__ C,
             int Mdim, int Ndim, int Kdim)
{
#if TC_OK
    extern __shared__ unsigned char smem[];
    const uint32_t smem_base = smem_u32(smem);
    const int tid  = threadIdx.x;
    const int wid  = tid >> 5;
    const int lane = tid & 31;
    const int wg   = tid >> 7;
    const int wg_tid = tid & 127;
    const int brow = blockIdx.y * 128;
    const int bcol = blockIdx.x * 128;
    const int NC   = Kdim / GT_KC;

    if (wid == 0) TC_ALLOC(smem_base, 256);
    if (tid == 0) mbar_init(smem_base + 8, 1);
    __syncthreads();
    uint32_t tmem_base;
    asm volatile("ld.shared.b32 %0, [%1];" : "=r"(tmem_base) : "r"(smem_base));

    const uint32_t TD  = tmem_base;
    const uint32_t TAH = tmem_base + 128;
    const uint32_t TAL = tmem_base + 160;
    const uint64_t dBH = mk_sw128_desc(smem_base + 1024);
    const uint64_t dBL = mk_sw128_desc(smem_base + 1024 + GT_TILEB);
    const uint32_t woff = ((uint32_t)wg_tid >> 5) << 21;

    uint32_t a_hi[32], a_lo[32];
    uint4    bq[16];

    auto load_regs = [&](int c) {
        const int k0 = c * GT_KC;
        if (wg == 1) {
#pragma unroll
            for (int t = 0; t < 2; t++) {
                const __nv_bfloat16* s = t ? Blo : Bhi;
#pragma unroll
                for (int e = 0; e < 8; e++) {
                    const int i  = wg_tid + e * 128;
                    const int r  = i >> 3;
                    const int kq = i & 7;
                    bq[t * 8 + e] =
                        *(const uint4*)(s + (size_t)(bcol + r) * Kdim + k0 + kq * 8);
                }
            }
        } else {
            const uint4* ph = (const uint4*)(Ahi + (size_t)(brow + wg_tid) * Kdim + k0);
            const uint4* pl = (const uint4*)(Alo + (size_t)(brow + wg_tid) * Kdim + k0);
#pragma unroll
            for (int e = 0; e < 8; e++) {
                uint4 vh = ph[e];
                a_hi[e * 4 + 0] = vh.x; a_hi[e * 4 + 1] = vh.y;
                a_hi[e * 4 + 2] = vh.z; a_hi[e * 4 + 3] = vh.w;
                uint4 vl = pl[e];
                a_lo[e * 4 + 0] = vl.x; a_lo[e * 4 + 1] = vl.y;
                a_lo[e * 4 + 2] = vl.z; a_lo[e * 4 + 3] = vl.w;
            }
        }
    };

    load_regs(0);

    for (int c = 0; c < NC; c++) {
        if (c > 0) mbar_wait(smem_base + 8, (uint32_t)((c - 1) & 1));

        if (wg == 1) {
#pragma unroll
            for (int t = 0; t < 2; t++) {
                unsigned char* dst = smem + 1024 + t * GT_TILEB;
#pragma unroll
                for (int e = 0; e < 8; e++) {
                    const int i  = wg_tid + e * 128;
                    const int r  = i >> 3;
                    const int kq = i & 7;
                    uint32_t off = r * 128 + kq * 16;
                    off ^= (off >> 3) & 0x70;
                    *(uint4*)(dst + off) = bq[t * 8 + e];
                }
            }
        } else {
            TCST32(TAH + woff, a_hi);
            TCST32(TAL + woff, a_lo);
            TC_WAIT_ST();
        }

        if (c + 1 < NC) load_regs(c + 1);

        TC_FENCE_BEFORE();
        FENCE_PROXY_ASYNC();
        __syncthreads();

        if (wid == 0) {
            TC_FENCE_AFTER();
            if (elect_one()) {
#pragma unroll
                for (int ksub = 0; ksub < 4; ksub++) {
                    const uint64_t o  = ksub * 2;
                    const uint32_t ac = ksub * 8;
                    uint32_t en0 = (c == 0 && ksub == 0) ? 0u : 1u;
                    tc_mma_f16_ts(TD, TAH + ac, dBH + o, GT_IDESC, en0);
                    tc_mma_f16_ts(TD, TAH + ac, dBL + o, GT_IDESC, 1u);
                    tc_mma_f16_ts(TD, TAL + ac, dBH + o, GT_IDESC, 1u);
                }
                tc_commit(smem_base + 8);
            }
        }
        __syncthreads();
    }

    mbar_wait(smem_base + 8, (uint32_t)((NC - 1) & 1));
    __syncthreads();
    TC_FENCE_AFTER();

    {
        const int r = (wid & 3) * 32 + lane;
        const int colbase = (wid >> 2) * 64;
        float* crow = C + (size_t)(brow + r) * Ndim + bcol;
#pragma unroll
        for (int cb = 0; cb < 2; cb++) {
            uint32_t dreg[32];
            TCLD32(dreg, TD + colbase + cb * 32);
            TC_WAIT_LD();
#pragma unroll
            for (int j = 0; j < 32; j += 4) {
                const int col = colbase + cb * 32 + j;
                float4 o;
                o.x = __uint_as_float(dreg[j + 0]) + bias[bcol + col + 0];
                o.y = __uint_as_float(dreg[j + 1]) + bias[bcol + col + 1];
                o.z = __uint_as_float(dreg[j + 2]) + bias[bcol + col + 2];
                o.w = __uint_as_float(dreg[j + 3]) + bias[bcol + col + 3];
                *(float4*)(crow + col) = o;
            }
        }
        TC_FENCE_BEFORE();
    }
    __syncthreads();
    if (wid == 0) TC_DEALLOC(tmem_base, 256);

#else
    const int tid  = threadIdx.x;
    const int brow = blockIdx.y * 128;
    const int bcol = blockIdx.x * 128;
    const int r = brow + (tid & 127);
    const int ch = (tid >> 7) * 64;
    for (int c0 = ch; c0 < ch + 64; c0 += 8) {
        float acc[8];
#pragma unroll
        for (int j = 0; j < 8; j++) acc[j] = 0.0f;
        for (int kk = 0; kk < Kdim; kk++) {
            float a = __bfloat162float(Ahi[(size_t)r * Kdim + kk])
                    + __bfloat162float(Alo[(size_t)r * Kdim + kk]);
#pragma unroll
            for (int j = 0; j < 8; j++) {
                const int cc = bcol + c0 + j;
                float b = __bfloat162float(Bhi[(size_t)cc * Kdim + kk])
                        + __bfloat162float(Blo[(size_t)cc * Kdim + kk]);
                acc[j] = fmaf(a, b, acc[j]);
            }
        }
#pragma unroll
        for (int j = 0; j < 8; j++)
            C[(size_t)r * Ndim + bcol + c0 + j] = acc[j] + bias[bcol + c0 + j];
    }
#endif
}

// ---------------------------------------------------------------------------
// Fused interleave-to-half + RoPE (unchanged)
// ---------------------------------------------------------------------------
__global__ __launch_bounds__(256) void rope_kernel(float* __restrict__ t,
                                                   int total_heads, int nh)
{
    const int gw = (blockIdx.x * blockDim.x + threadIdx.x) >> 5;
    if (gw >= total_heads) return;
    const int lane = threadIdx.x & 31;
    const int s = (gw / nh) % S_;

    float* base = t + (size_t)gw * 128;
    float e0 = base[2 * lane],      o0 = base[2 * lane + 1];
    float e1 = base[2 * lane + 64], o1 = base[2 * lane + 65];
    __syncwarp();

    const float pos = (float)s;
    const float f0 = powf(10000.0f, -((float)lane) / 64.0f);
    const float f1 = powf(10000.0f, -((float)(lane + 32)) / 64.0f);
    float s0, c0, s1, c1;
    sincosf(pos * f0, &s0, &c0);
    sincosf(pos * f1, &s1, &c1);

    base[lane]      = e0 * c0 - o0 * s0;
    base[lane + 64] = e0 * s0 + o0 * c0;
    base[lane + 32] = e1 * c1 - o1 * s1;
    base[lane + 96] = e1 * s1 + o1 * c1;
}

// ===========================================================================
// Tensor-core causal flash attention (hi/lo bf16, fp32 TMEM accumulators).
// grid (16 q-tiles of 128, 64 b*h), 128 threads, 1 CTA/SM (TMEM 512 cols).
// TMEM: S=0..127, O=128..255, Qhi=256..319, Qlo=320..383, Phi=384..447,
//       Plo=448..511. Per kv-tile (128): S-MMAs (2 d-chunks x 12, validated
//       R14 envelope) -> softmax in registers (row = thread) -> P hi/lo TCST
//       -> O alpha-rescale (TMEM RMW) -> PV-MMAs (2 kv-chunks x 12, V^T from
//       pre-transposed global). Fully serialized (the twice-validated schedule).
// ===========================================================================
#define FT_TILEB  (128 * 128)            // 16 KB per B tile (128 rows x 64 bf16)
#define FT_SMEM   (120 * 1024)           // pad -> 1 CTA/SM

__global__ __launch_bounds__(128, 1)
void flash_tc(const __nv_bfloat16* __restrict__ qhi,
              const __nv_bfloat16* __restrict__ qlo,
              const __nv_bfloat16* __restrict__ khi,
              const __nv_bfloat16* __restrict__ klo,
              const __nv_bfloat16* __restrict__ vthi,
              const __nv_bfloat16* __restrict__ vtlo,
              float* __restrict__ ctx)
{
#if TC_OK
    extern __shared__ unsigned char smem[];
    const uint32_t smem_base = smem_u32(smem);
    const int tid  = threadIdx.x;       // 0..127 (one warpgroup)
    const int wid  = tid >> 5;
    const int qt   = blockIdx.x;        // 0..15
    const int bh   = blockIdx.y;        // 0..63
    const int b    = bh >> 5;
    const int h    = bh & 31;
    const int hkv  = h >> 2;
    const uint32_t woff = ((uint32_t)tid >> 5) << 21;

    if (wid == 0) TC_ALLOC(smem_base, 512);
    if (tid == 0) mbar_init(smem_base + 8, 1);
    __syncthreads();
    uint32_t tmem_base;
    asm volatile("ld.shared.b32 %0, [%1];" : "=r"(tmem_base) : "r"(smem_base));

    const uint32_t TS  = tmem_base;          // S accum: 128 cols
    const uint32_t TO  = tmem_base + 128;    // O accum: 128 cols
    const uint32_t TQH = tmem_base + 256;    // Q hi: 64 cols
    const uint32_t TQL = tmem_base + 320;    // Q lo: 64 cols
    const uint32_t TPH = tmem_base + 384;    // P hi: 64 cols
    const uint32_t TPL = tmem_base + 448;    // P lo: 64 cols
    const uint64_t dH = mk_sw128_desc(smem_base + 1024);
    const uint64_t dL = mk_sw128_desc(smem_base + 1024 + FT_TILEB);

    const int q_global = qt * 128 + tid;

    // ---- stage Q hi/lo (row = tid): 128 bf16 = 64 cols each ----------------
    {
        uint32_t r0[32], r1[32];
        const uint4* ph = (const uint4*)(qhi + ((size_t)(b * S_ + q_global) * H_ + h) * D_);
        const uint4* pl = (const uint4*)(qlo + ((size_t)(b * S_ + q_global) * H_ + h) * D_);
#pragma unroll
        for (int e = 0; e < 8; e++) {
            uint4 v = ph[e];
            r0[e*4+0] = v.x; r0[e*4+1] = v.y; r0[e*4+2] = v.z; r0[e*4+3] = v.w;
            uint4 w = ph[e + 8];
            r1[e*4+0] = w.x; r1[e*4+1] = w.y; r1[e*4+2] = w.z; r1[e*4+3] = w.w;
        }
        TCST32(TQH + woff, r0);
        TCST32(TQH + 32 + woff, r1);
#pragma unroll
        for (int e = 0; e < 8; e++) {
            uint4 v = pl[e];
            r0[e*4+0] = v.x; r0[e*4+1] = v.y; r0[e*4+2] = v.z; r0[e*4+3] = v.w;
            uint4 w = pl[e + 8];
            r1[e*4+0] = w.x; r1[e*4+1] = w.y; r1[e*4+2] = w.z; r1[e*4+3] = w.w;
        }
        TCST32(TQL + woff, r0);
        TCST32(TQL + 32 + woff, r1);
        TC_WAIT_ST();
    }

    float m = -INFINITY, l = 0.0f;
    int   nc = 0;                         // commit counter
    const float scale = 0.08838834764831845f;   // 1/sqrt(128)

    for (int jt = 0; jt <= qt; jt++) {
        const int kv0 = jt * 128;

        // ================= S = Q @ K^T (2 d-chunks) =========================
#pragma unroll 1
        for (int ch = 0; ch < 2; ch++) {
            // K tile rows (row = kv = tid): 64 bf16 hi + lo, SW128 swizzle
            const __nv_bfloat16* sh = khi + ((size_t)(b * S_ + kv0 + tid) * HKV_ + hkv) * D_ + ch * 64;
            const __nv_bfloat16* sl = klo + ((size_t)(b * S_ + kv0 + tid) * HKV_ + hkv) * D_ + ch * 64;
            unsigned char* dsth = smem + 1024;
            unsigned char* dstl = smem + 1024 + FT_TILEB;
#pragma unroll
            for (int kq = 0; kq < 8; kq++) {
                uint32_t off = tid * 128 + kq * 16;
                off ^= (off >> 3) & 0x70;
                *(uint4*)(dsth + off) = *(const uint4*)(sh + kq * 8);
                *(uint4*)(dstl + off) = *(const uint4*)(sl + kq * 8);
            }
            TC_FENCE_BEFORE();
            FENCE_PROXY_ASYNC();
            __syncthreads();
            if (wid == 0) {
                TC_FENCE_AFTER();
                if (elect_one()) {
#pragma unroll
                    for (int ksub = 0; ksub < 4; ksub++) {
                        const uint64_t o  = ksub * 2;
                        const uint32_t ac = ch * 32 + ksub * 8;
                        uint32_t en0 = (ch == 0 && ksub == 0) ? 0u : 1u;  // fresh S
                        tc_mma_f16_ts(TS, TQH + ac, dH + o, GT_IDESC, en0);
                        tc_mma_f16_ts(TS, TQH + ac, dL + o, GT_IDESC, 1u);
                        tc_mma_f16_ts(TS, TQL + ac, dH + o, GT_IDESC, 1u);
                    }
                    tc_commit(smem_base + 8);
                }
            }
            nc++;
            mbar_wait(smem_base + 8, (uint32_t)((nc - 1) & 1));
            __syncthreads();
        }
        TC_FENCE_AFTER();

        // ================= softmax (row = tid) ==============================
        float sv[128];
#pragma unroll
        for (int cb = 0; cb < 4; cb++) {
            uint32_t tmp[32];
            TCLD32(tmp, TS + cb * 32);
            TC_WAIT_LD();
#pragma unroll
            for (int j = 0; j < 32; j++) {
                float x = __uint_as_float(tmp[j]) * scale;
                if (jt == qt && (kv0 + cb * 32 + j) > q_global) x = -1e30f;
                sv[cb * 32 + j] = x;
            }
        }
        float mnew = m;
#pragma unroll
        for (int i = 0; i < 128; i++) mnew = fmaxf(mnew, sv[i]);
        const float alpha = __expf(m - mnew);     // jt==0: exp(-inf)=0
        float sum = 0.0f;
#pragma unroll
        for (int i = 0; i < 128; i++) {
            float p = __expf(sv[i] - mnew);
            sv[i] = p;
            sum += p;
        }
        l = l * alpha + sum;
        m = mnew;

        // ---- P hi/lo -> TMEM (2 blocks of 32 cols each) --------------------
#pragma unroll 1
        for (int blk = 0; blk < 2; blk++) {
            uint32_t phr[32], plr[32];
#pragma unroll
            for (int e = 0; e < 32; e++) {
                float f0 = sv[blk * 64 + 2 * e];
                float f1 = sv[blk * 64 + 2 * e + 1];
                __nv_bfloat16 h0 = __float2bfloat16(f0);
                __nv_bfloat16 h1 = __float2bfloat16(f1);
                __nv_bfloat16 l0 = __float2bfloat16(f0 - __bfloat162float(h0));
                __nv_bfloat16 l1 = __float2bfloat16(f1 - __bfloat162float(h1));
                union { __nv_bfloat162 b2; uint32_t u; } uh, ul;
                uh.b2 = __nv_bfloat162(h0, h1);
                ul.b2 = __nv_bfloat162(l0, l1);
                phr[e] = uh.u;
                plr[e] = ul.u;
            }
            TCST32(TPH + blk * 32 + woff, phr);
            TCST32(TPL + blk * 32 + woff, plr);
        }
        TC_WAIT_ST();

        // ---- rescale O by alpha (TMEM RMW), skip at jt==0 ------------------
        if (jt > 0) {
#pragma unroll
            for (int cb = 0; cb < 4; cb++) {
                uint32_t tmp[32];
                TCLD32(tmp, TO + cb * 32);
                TC_WAIT_LD();
#pragma unroll
                for (int j = 0; j < 32; j++)
                    tmp[j] = __float_as_uint(__uint_as_float(tmp[j]) * alpha);
                TCST32(TO + cb * 32 + woff, tmp);
                TC_WAIT_ST();
            }
        }

        // ================= O += P @ V (2 kv-chunks) =========================
#pragma unroll 1
        for (int ch = 0; ch < 2; ch++) {
            // V^T tile rows (row = d = tid): 64 bf16 hi + lo from pre-transposed
            const __nv_bfloat16* sh = vthi + ((size_t)(b * HKV_ + hkv) * D_ + tid) * S_ + kv0 + ch * 64;
            const __nv_bfloat16* sl = vtlo + ((size_t)(b * HKV_ + hkv) * D_ + tid) * S_ + kv0 + ch * 64;
            unsigned char* dsth = smem + 1024;
            unsigned char* dstl = smem + 1024 + FT_TILEB;
#pragma unroll
            for (int kq = 0; kq < 8; kq++) {
                uint32_t off = tid * 128 + kq * 16;
                off ^= (off >> 3) & 0x70;
                *(uint4*)(dsth + off) = *(const uint4*)(sh + kq * 8);
                *(uint4*)(dstl + off) = *(const uint4*)(sl + kq * 8);
            }
            TC_FENCE_BEFORE();
            FENCE_PROXY_ASYNC();
            __syncthreads();
            if (wid == 0) {
                TC_FENCE_AFTER();
                if (elect_one()) {
#pragma unroll
                    for (int ksub = 0; ksub < 4; ksub++) {
                        const uint64_t o  = ksub * 2;
                        const uint32_t ac = ch * 32 + ksub * 8;
                        uint32_t en0 = (jt == 0 && ch == 0 && ksub == 0) ? 0u : 1u;
                        tc_mma_f16_ts(TO, TPH + ac, dH + o, GT_IDESC, en0);
                        tc_mma_f16_ts(TO, TPH + ac, dL + o, GT_IDESC, 1u);
                        tc_mma_f16_ts(TO, TPL + ac, dH + o, GT_IDESC, 1u);
                    }
                    tc_commit(smem_base + 8);
                }
            }
            nc++;
            mbar_wait(smem_base + 8, (uint32_t)((nc - 1) & 1));
            __syncthreads();
        }
        TC_FENCE_AFTER();
    }

    // ---- epilogue: O / l -> ctx -------------------------------------------
    {
        const float inv = 1.0f / l;
        float* outp = ctx + ((size_t)(b * S_ + q_global) * H_ + h) * D_;
#pragma unroll
        for (int cb = 0; cb < 4; cb++) {
            uint32_t tmp[32];
            TCLD32(tmp, TO + cb * 32);
            TC_WAIT_LD();
#pragma unroll
            for (int j = 0; j < 32; j += 4) {
                float4 o;
                o.x = __uint_as_float(tmp[j + 0]) * inv;
                o.y = __uint_as_float(tmp[j + 1]) * inv;
                o.z = __uint_as_float(tmp[j + 2]) * inv;
                o.w = __uint_as_float(tmp[j + 3]) * inv;
                *(float4*)(outp + cb * 32 + j) = o;
            }
        }
        TC_FENCE_BEFORE();
    }
    __syncthreads();
    if (wid == 0) TC_DEALLOC(tmem_base, 512);

#else  // -------- portable fallback (non-'a' PTX pass only; never runs) -----
    const int tid  = threadIdx.x;
    const int qt   = blockIdx.x;
    const int bh   = blockIdx.y;
    const int b    = bh >> 5;
    const int h    = bh & 31;
    const int hkv  = h >> 2;
    const int q_global = qt * 128 + tid;
    const float scale = 0.08838834764831845f;

    float o[128];
#pragma unroll
    for (int d = 0; d < 128; d++) o[d] = 0.0f;
    float m = -INFINITY, l = 0.0f;
    for (int kv = 0; kv <= q_global; kv++) {
        float s = 0.0f;
        for (int d = 0; d < 128; d++) {
            float qv = __bfloat162float(qhi[((size_t)(b*S_+q_global)*H_+h)*D_+d])
                     + __bfloat162float(qlo[((size_t)(b*S_+q_global)*H_+h)*D_+d]);
            float kvv = __bfloat162float(khi[((size_t)(b*S_+kv)*HKV_+hkv)*D_+d])
                      + __bfloat162float(klo[((size_t)(b*S_+kv)*HKV_+hkv)*D_+d]);
            s += qv * kvv;
        }
        s *= scale;
        float mn = fmaxf(m, s);
        float al = expf(m - mn);
        float p  = expf(s - mn);
        for (int d = 0; d < 128; d++) {
            float vv = __bfloat162float(vthi[((size_t)(b*HKV_+hkv)*D_+d)*S_+kv])
                     + __bfloat162float(vtlo[((size_t)(b*HKV_+hkv)*D_+d)*S_+kv]);
            o[d] = o[d] * al + p * vv;
        }
        l = l * al + p;
        m = mn;
    }
    for (int d = 0; d < 128; d++)
        ctx[((size_t)(b*S_+q_global)*H_+h)*D_+d] = o[d] / l;
#endif
}

// ---------------------------------------------------------------------------
extern "C" void kernel_launch(void* const* d_in, const int* in_sizes, int n_in,
                              void* d_out, int out_size)
{
    const float* x    = (const float*)d_in[0];
    const float* wq_w = (const float*)d_in[1];
    const float* wq_b = (const float*)d_in[2];
    const float* wk_w = (const float*)d_in[3];
    const float* wk_b = (const float*)d_in[4];
    const float* wv_w = (const float*)d_in[5];
    const float* wv_b = (const float*)d_in[6];
    const float* wo_w = (const float*)d_in[7];
    const float* wo_b = (const float*)d_in[8];

    float *q, *k, *v, *ctx;
    __nv_bfloat16 *ahi, *alo, *khi, *klo, *vthi, *vtlo;
    __nv_bfloat16 *wqh, *wql, *wkh, *wkl, *wvh, *wvl, *woh, *wol;
    cudaGetSymbolAddress((void**)&q,    g_q);
    cudaGetSymbolAddress((void**)&k,    g_k);
    cudaGetSymbolAddress((void**)&v,    g_v);
    cudaGetSymbolAddress((void**)&ctx,  g_ctx);
    cudaGetSymbolAddress((void**)&ahi,  g_ahi);
    cudaGetSymbolAddress((void**)&alo,  g_alo);
    cudaGetSymbolAddress((void**)&khi,  g_khi);
    cudaGetSymbolAddress((void**)&klo,  g_klo);
    cudaGetSymbolAddress((void**)&vthi, g_vthi);
    cudaGetSymbolAddress((void**)&vtlo, g_vtlo);
    cudaGetSymbolAddress((void**)&wqh,  g_wqt_hi);
    cudaGetSymbolAddress((void**)&wql,  g_wqt_lo);
    cudaGetSymbolAddress((void**)&wkh,  g_wkt_hi);
    cudaGetSymbolAddress((void**)&wkl,  g_wkt_lo);
    cudaGetSymbolAddress((void**)&wvh,  g_wvt_hi);
    cudaGetSymbolAddress((void**)&wvl,  g_wvt_lo);
    cudaGetSymbolAddress((void**)&woh,  g_wot_hi);
    cudaGetSymbolAddress((void**)&wol,  g_wot_lo);

    cudaFuncSetAttribute(gemm_tc, cudaFuncAttributeMaxDynamicSharedMemorySize, GT_SMEM);
    cudaFuncSetAttribute(flash_tc, cudaFuncAttributeMaxDynamicSharedMemorySize, FT_SMEM);

    const dim3 tb(32, 8);
    // weight transpose + bf16 split
    transpose_convert<<<dim3(E_ / 32,   E_ / 32), tb>>>(wq_w, wqh, wql, E_, E_);
    transpose_convert<<<dim3(NKV_ / 32, E_ / 32), tb>>>(wk_w, wkh, wkl, E_, NKV_);
    transpose_convert<<<dim3(NKV_ / 32, E_ / 32), tb>>>(wv_w, wvh, wvl, E_, NKV_);
    transpose_convert<<<dim3(E_ / 32,   E_ / 32), tb>>>(wo_w, woh, wol, E_, E_);
    // activation split
    convert_hilo<<<(M_ * E_ / 4) / 256, 256>>>(x, ahi, alo, M_ * E_ / 4);

    // QKV projections on tcgen05 (R14 pipeline)
    gemm_tc<<<dim3(E_ / 128,   M_ / 128), 256, GT_SMEM>>>(ahi, alo, wqh, wql, wq_b, q, M_, E_,   E_);
    gemm_tc<<<dim3(NKV_ / 128, M_ / 128), 256, GT_SMEM>>>(ahi, alo, wkh, wkl, wk_b, k, M_, NKV_, E_);
    gemm_tc<<<dim3(NKV_ / 128, M_ / 128), 256, GT_SMEM>>>(ahi, alo, wvh, wvl, wv_b, v, M_, NKV_, E_);

    // RoPE on q and k (in place)
    rope_kernel<<<(M_ * H_   * 32) / 256, 256>>>(q, M_ * H_,   H_);
    rope_kernel<<<(M_ * HKV_ * 32) / 256, 256>>>(k, M_ * HKV_, HKV_);

    // attention operand prep: q/k hi-lo split (ahi reused for q), V transpose
    convert_hilo<<<(M_ * E_ / 4) / 256, 256>>>(q, ahi, alo, M_ * E_ / 4);
    convert_hilo<<<(M_ * NKV_ / 4) / 256, 256>>>(k, khi, klo, M_ * NKV_ / 4);
    vtrans_convert<<<dim3(S_ / 32, D_ / 32, B_ * HKV_), tb>>>(v, vthi, vtlo);

    // tensor-core flash attention
    flash_tc<<<dim3(S_ / 128, B_ * H_), 128, FT_SMEM>>>(ahi, alo, khi, klo,
                                                        vthi, vtlo, ctx);

    // Output projection on tcgen05
    convert_hilo<<<(M_ * E_ / 4) / 256, 256>>>(ctx, ahi, alo, M_ * E_ / 4);
    gemm_tc<<<dim3(E_ / 128, M_ / 128), 256, GT_SMEM>>>(ahi, alo, woh, wol, wo_b,
                                                        (float*)d_out, M_, E_, E_);
}